// round 11
// baseline (speedup 1.0000x reference)
#include <cuda_runtime.h>
#include <cuda_bf16.h>
#include <cstdint>

#define N_NODES 20000
#define N_PAD   20096                 // padded rows for OOB-safe cp.async
#define E_EDGES 320000
#define E_TOT   (E_EDGES + N_NODES)
#define IN_C    256
#define HID     64
#define HEADS   4
#define OUT_C   64
#define F1      (HEADS * HID)         // 256

// ---------------- scratch (device globals, no allocs) ----------------
__device__ float g_h1[(size_t)N_NODES * F1];
__device__ float g_out1[(size_t)N_NODES * F1];
__device__ float g_h2[(size_t)N_NODES * OUT_C];
__device__ float g_e1s[N_NODES * HEADS];
__device__ float g_e1d[N_NODES * HEADS];
__device__ float g_e2s[N_NODES];
__device__ float g_e2d[N_NODES];
__device__ int   g_cnt[N_NODES];
__device__ int   g_off[N_NODES + 1];
__device__ int   g_rank[E_EDGES];
__device__ int   g_csr[E_TOT];
__device__ __nv_bfloat16 g_xh[(size_t)N_PAD * IN_C];
__device__ __nv_bfloat16 g_xl[(size_t)N_PAD * IN_C];
__device__ __nv_bfloat16 g_wh[IN_C * F1];   // n-major: [n][k]
__device__ __nv_bfloat16 g_wl[IN_C * F1];

// ================= CSR build =================
__global__ void initcnt_kernel(int* __restrict__ cnt) {
    int i = blockIdx.x * blockDim.x + threadIdx.x;
    if (i < N_NODES) cnt[i] = 0;
}
__global__ void count_kernel(const int* __restrict__ ei, int* __restrict__ cnt,
                             int* __restrict__ rank) {
    int e = (blockIdx.x * blockDim.x + threadIdx.x) * 4;
    if (e >= E_EDGES) return;
    int4 d4 = *(const int4*)(ei + E_EDGES + e);
    int4 r4;
    r4.x = atomicAdd(&cnt[d4.x], 1);
    r4.y = atomicAdd(&cnt[d4.y], 1);
    r4.z = atomicAdd(&cnt[d4.z], 1);
    r4.w = atomicAdd(&cnt[d4.w], 1);
    *(int4*)(rank + e) = r4;
}
__global__ void __launch_bounds__(1024) scan_kernel(const int* __restrict__ cnt,
                                                    int* __restrict__ off,
                                                    int* __restrict__ csr) {
    __shared__ int wsum[32];
    const int CH = (N_NODES + 1023) / 1024;   // 20
    int tid = threadIdx.x;
    int lane = tid & 31, warp = tid >> 5;
    int base = tid * CH;
    int local[CH];
    int sum = 0;
    #pragma unroll
    for (int i = 0; i < CH; i++) {
        int idx = base + i;
        int v = idx < N_NODES ? (cnt[idx] + 1) : 0;
        local[i] = sum;
        sum += v;
    }
    int inc = sum;
    #pragma unroll
    for (int o = 1; o < 32; o <<= 1) {
        int t = __shfl_up_sync(0xFFFFFFFFu, inc, o);
        if (lane >= o) inc += t;
    }
    if (lane == 31) wsum[warp] = inc;
    __syncthreads();
    if (warp == 0) {
        int w = wsum[lane];
        #pragma unroll
        for (int o = 1; o < 32; o <<= 1) {
            int t = __shfl_up_sync(0xFFFFFFFFu, w, o);
            if (lane >= o) w += t;
        }
        wsum[lane] = w;
    }
    __syncthreads();
    int prev = inc - sum + (warp ? wsum[warp - 1] : 0);
    #pragma unroll
    for (int i = 0; i < CH; i++) {
        int idx = base + i;
        if (idx < N_NODES) {
            int v = prev + local[i];
            off[idx] = v;
            csr[v] = idx;   // self-loop at slot 0
        }
    }
    if (tid == 1023) off[N_NODES] = prev + sum;
}
__global__ void fill_kernel(const int* __restrict__ ei, const int* __restrict__ off,
                            const int* __restrict__ rank, int* __restrict__ csr) {
    int e = (blockIdx.x * blockDim.x + threadIdx.x) * 4;
    if (e >= E_EDGES) return;
    int4 s4 = *(const int4*)(ei + e);
    int4 d4 = *(const int4*)(ei + E_EDGES + e);
    int4 r4 = *(const int4*)(rank + e);
    csr[off[d4.x] + 1 + r4.x] = s4.x;
    csr[off[d4.y] + 1 + r4.y] = s4.y;
    csr[off[d4.z] + 1 + r4.z] = s4.z;
    csr[off[d4.w] + 1 + r4.w] = s4.w;
}

// ================= fp32 -> bf16 hi/lo prepass =================
__global__ void convx_kernel(const float* __restrict__ x,
                             __nv_bfloat16* __restrict__ xh,
                             __nv_bfloat16* __restrict__ xl) {
    size_t i = (size_t)(blockIdx.x * blockDim.x + threadIdx.x) * 4;
    if (i >= (size_t)N_PAD * IN_C) return;
    float4 v = make_float4(0.f, 0.f, 0.f, 0.f);
    if (i < (size_t)N_NODES * IN_C) v = *(const float4*)(x + i);
    __nv_bfloat16 h0 = __float2bfloat16(v.x), h1 = __float2bfloat16(v.y);
    __nv_bfloat16 h2 = __float2bfloat16(v.z), h3 = __float2bfloat16(v.w);
    *(__nv_bfloat162*)(xh + i)     = __nv_bfloat162(h0, h1);
    *(__nv_bfloat162*)(xh + i + 2) = __nv_bfloat162(h2, h3);
    *(__nv_bfloat162*)(xl + i) = __nv_bfloat162(
        __float2bfloat16(v.x - __bfloat162float(h0)),
        __float2bfloat16(v.y - __bfloat162float(h1)));
    *(__nv_bfloat162*)(xl + i + 2) = __nv_bfloat162(
        __float2bfloat16(v.z - __bfloat162float(h2)),
        __float2bfloat16(v.w - __bfloat162float(h3)));
}
__global__ void convw_kernel(const float* __restrict__ w,
                             __nv_bfloat16* __restrict__ wh,
                             __nv_bfloat16* __restrict__ wl) {
    int i = blockIdx.x * blockDim.x + threadIdx.x;
    if (i >= IN_C * F1) return;
    int n = i >> 8, k = i & 255;
    float v = w[(size_t)k * F1 + n];
    __nv_bfloat16 h = __float2bfloat16(v);
    wh[i] = h;
    wl[i] = __float2bfloat16(v - __bfloat162float(h));
}

// ---------------- mma / ldmatrix / cp.async helpers ----------------
__device__ __forceinline__ void mma_bf16(float* d, const uint32_t* a,
                                         const uint32_t* b, const float* c) {
    asm volatile(
        "mma.sync.aligned.m16n8k16.row.col.f32.bf16.bf16.f32 "
        "{%0,%1,%2,%3}, {%4,%5,%6,%7}, {%8,%9}, {%10,%11,%12,%13};"
        : "=f"(d[0]), "=f"(d[1]), "=f"(d[2]), "=f"(d[3])
        : "r"(a[0]), "r"(a[1]), "r"(a[2]), "r"(a[3]),
          "r"(b[0]), "r"(b[1]),
          "f"(c[0]), "f"(c[1]), "f"(c[2]), "f"(c[3]));
}
__device__ __forceinline__ void ldm_x4(uint32_t* r, uint32_t addr) {
    asm volatile("ldmatrix.sync.aligned.m8n8.x4.shared.b16 {%0,%1,%2,%3}, [%4];"
                 : "=r"(r[0]), "=r"(r[1]), "=r"(r[2]), "=r"(r[3]) : "r"(addr));
}
__device__ __forceinline__ uint32_t smem_u32(const void* p) {
    uint32_t a;
    asm("{ .reg .u64 t; cvta.to.shared.u64 t, %1; cvt.u32.u64 %0, t; }" : "=r"(a) : "l"(p));
    return a;
}
__device__ __forceinline__ void cp16(uint32_t s, const void* g) {
    asm volatile("cp.async.cg.shared.global [%0], [%1], 16;" :: "r"(s), "l"(g) : "memory");
}
#define CP_COMMIT() asm volatile("cp.async.commit_group;" ::: "memory")

// ---------- layer-1 GEMM: HMMA, double-buffered cp.async, pre-converted bf16 ----------
#define ASTRB 80                     // bytes per 32-k row (padded for ldmatrix banks)
#define ARR   (128 * ASTRB)          // 10240 per array
#define STAGE (4 * ARR)              // Ah, Al, Bh, Bl
__global__ void __launch_bounds__(256)
gemm1_mma_kernel(const __nv_bfloat16* __restrict__ Xh, const __nv_bfloat16* __restrict__ Xl,
                 const __nv_bfloat16* __restrict__ Wh, const __nv_bfloat16* __restrict__ Wl,
                 float* __restrict__ C, int M,
                 const float* __restrict__ a_src, const float* __restrict__ a_dst,
                 float* __restrict__ es, float* __restrict__ ed) {
    extern __shared__ char smem[];
    __shared__ float AS[128], AD[128];

    const int tid = threadIdx.x;
    const int w = tid >> 5, lane = tid & 31;
    const int q = lane & 3, r = lane >> 2;
    const int bm = blockIdx.y * 128;
    const int bn = blockIdx.x * 128;
    const int wrow = w * 16;

    if (tid < 128) {
        AS[tid] = a_src[bn + tid];
        AD[tid] = a_dst[bn + tid];
    }
    const uint32_t sbase = smem_u32(smem);

    // per-thread cp.async assignment: row = tid>>1, 32B half = tid&1
    const int lrow = tid >> 1;
    const int lce = (tid & 1) * 16;                 // bf16 elem offset in 32-k row
    const size_t gaA = (size_t)(bm + lrow) * IN_C + lce;
    const size_t gaB = (size_t)(bn + lrow) * IN_C + lce;
    const uint32_t saoff = (uint32_t)(lrow * ASTRB + lce * 2);

    // ldmatrix lane addresses
    const int ln  = lane & 7;
    const int sel = lane >> 3;
    const uint32_t a_off = (uint32_t)((wrow + ln + (sel & 1) * 8) * ASTRB + (sel >> 1) * 16);
    const uint32_t b_off = (uint32_t)(((sel >> 1) * 8 + ln) * ASTRB + (sel & 1) * 16);

    float acc[16][4];
    #pragma unroll
    for (int t = 0; t < 16; t++)
        #pragma unroll
        for (int j = 0; j < 4; j++) acc[t][j] = 0.f;

    // ---- issue stage loads for chunk kc into stage s ----
    auto issue = [&](int kc, int s) {
        const int k0 = kc * 32;
        const uint32_t st = sbase + s * STAGE;
        uint32_t sa = st + saoff;
        cp16(sa,            Xh + gaA + k0);
        cp16(sa + 16,       Xh + gaA + k0 + 8);
        cp16(sa + ARR,      Xl + gaA + k0);
        cp16(sa + ARR + 16, Xl + gaA + k0 + 8);
        sa += 2 * ARR;
        cp16(sa,            Wh + gaB + k0);
        cp16(sa + 16,       Wh + gaB + k0 + 8);
        cp16(sa + ARR,      Wl + gaB + k0);
        cp16(sa + ARR + 16, Wl + gaB + k0 + 8);
    };

    issue(0, 0); CP_COMMIT();
    issue(1, 1); CP_COMMIT();

    for (int kc = 0; kc < 8; kc++) {
        const int s = kc & 1;
        if (kc < 7) asm volatile("cp.async.wait_group 1;" ::: "memory");
        else        asm volatile("cp.async.wait_group 0;" ::: "memory");
        __syncthreads();
        const uint32_t st = sbase + s * STAGE;
        #pragma unroll
        for (int ks = 0; ks < 2; ks++) {
            const uint32_t koff = (uint32_t)(ks * 32);   // 16 elems * 2B
            uint32_t ah[4], al[4];
            ldm_x4(ah, st + a_off + koff);
            ldm_x4(al, st + ARR + a_off + koff);
            #pragma unroll
            for (int tp = 0; tp < 8; tp++) {
                const int t = tp * 2;
                uint32_t bh4[4], bl4[4];
                const uint32_t ba = st + 2 * ARR + b_off + koff + (uint32_t)t * (8 * ASTRB);
                ldm_x4(bh4, ba);
                ldm_x4(bl4, ba + ARR);
                mma_bf16(acc[t],     ah, &bh4[0], acc[t]);
                mma_bf16(acc[t],     ah, &bl4[0], acc[t]);
                mma_bf16(acc[t],     al, &bh4[0], acc[t]);
                mma_bf16(acc[t + 1], ah, &bh4[2], acc[t + 1]);
                mma_bf16(acc[t + 1], ah, &bl4[2], acc[t + 1]);
                mma_bf16(acc[t + 1], al, &bh4[2], acc[t + 1]);
            }
        }
        __syncthreads();
        if (kc + 2 < 8) { issue(kc + 2, s); CP_COMMIT(); }
    }

    // ---- epilogue: store C + fused attention dots ----
    int row0 = bm + wrow + r;
    int row1 = row0 + 8;
    float sd0[2] = {0.f, 0.f}, sd1[2] = {0.f, 0.f};
    float dd0[2] = {0.f, 0.f}, dd1[2] = {0.f, 0.f};
    #pragma unroll
    for (int t = 0; t < 16; t++) {
        int c0 = t * 8 + q * 2;
        int hh = t >> 3;
        sd0[hh] += acc[t][0] * AS[c0] + acc[t][1] * AS[c0 + 1];
        dd0[hh] += acc[t][0] * AD[c0] + acc[t][1] * AD[c0 + 1];
        sd1[hh] += acc[t][2] * AS[c0] + acc[t][3] * AS[c0 + 1];
        dd1[hh] += acc[t][2] * AD[c0] + acc[t][3] * AD[c0 + 1];
        if (row0 < M)
            *(float2*)(C + (size_t)row0 * F1 + bn + c0) = make_float2(acc[t][0], acc[t][1]);
        if (row1 < M)
            *(float2*)(C + (size_t)row1 * F1 + bn + c0) = make_float2(acc[t][2], acc[t][3]);
    }
    #pragma unroll
    for (int o = 1; o < 4; o <<= 1) {
        #pragma unroll
        for (int hh = 0; hh < 2; hh++) {
            sd0[hh] += __shfl_xor_sync(0xFFFFFFFFu, sd0[hh], o);
            sd1[hh] += __shfl_xor_sync(0xFFFFFFFFu, sd1[hh], o);
            dd0[hh] += __shfl_xor_sync(0xFFFFFFFFu, dd0[hh], o);
            dd1[hh] += __shfl_xor_sync(0xFFFFFFFFu, dd1[hh], o);
        }
    }
    if (q == 0) {
        int hb = blockIdx.x * 2;
        if (row0 < M) {
            es[row0 * HEADS + hb]     = sd0[0];
            es[row0 * HEADS + hb + 1] = sd0[1];
            ed[row0 * HEADS + hb]     = dd0[0];
            ed[row0 * HEADS + hb + 1] = dd0[1];
        }
        if (row1 < M) {
            es[row1 * HEADS + hb]     = sd1[0];
            es[row1 * HEADS + hb + 1] = sd1[1];
            ed[row1 * HEADS + hb]     = dd1[0];
            ed[row1 * HEADS + hb + 1] = dd1[1];
        }
    }
}

// ---------- layer-2 GEMM (scalar f32x2, BN=64) ----------
__device__ __forceinline__ unsigned long long pack2(float lo, float hi) {
    unsigned long long r;
    asm("mov.b64 %0, {%1, %2};" : "=l"(r) : "f"(lo), "f"(hi));
    return r;
}
__device__ __forceinline__ void unpack2(unsigned long long v, float& lo, float& hi) {
    asm("mov.b64 {%0, %1}, %2;" : "=f"(lo), "=f"(hi) : "l"(v));
}
__device__ __forceinline__ unsigned long long fma2(unsigned long long a,
                                                   unsigned long long b,
                                                   unsigned long long c) {
    unsigned long long d;
    asm("fma.rn.f32x2 %0, %1, %2, %3;" : "=l"(d) : "l"(a), "l"(b), "l"(c));
    return d;
}
__global__ void __launch_bounds__(128)
sgemm2_kernel(const float* __restrict__ A, const float* __restrict__ B,
              float* __restrict__ C, int M, int K,
              const float* __restrict__ a_src, const float* __restrict__ a_dst,
              float* __restrict__ es, float* __restrict__ ed) {
    const int N = 64;
    __shared__ float As[16][132];
    __shared__ float Bs[16][68];
    const int bm = blockIdx.y * 128;
    const int tid = threadIdx.x;
    const int tm = (tid >> 3) * 8;
    const int tn = (tid & 7) * 8;

    unsigned long long acc[8][4];
    #pragma unroll
    for (int i = 0; i < 8; i++)
        #pragma unroll
        for (int j = 0; j < 4; j++) acc[i][j] = 0ull;

    for (int k0 = 0; k0 < K; k0 += 16) {
        {
            int r = tid;
            int row = bm + r;
            #pragma unroll
            for (int cc = 0; cc < 4; cc++) {
                int c = cc * 4;
                float4 v = make_float4(0.f, 0.f, 0.f, 0.f);
                if (row < M) v = *(const float4*)(A + (size_t)row * K + k0 + c);
                As[c + 0][r] = v.x; As[c + 1][r] = v.y;
                As[c + 2][r] = v.z; As[c + 3][r] = v.w;
            }
        }
        {
            int r = tid >> 3;
            int c = (tid & 7) * 8;
            const float* src = B + (size_t)(k0 + r) * N + c;
            *(float4*)&Bs[r][c] = *(const float4*)src;
            *(float4*)&Bs[r][c + 4] = *(const float4*)(src + 4);
        }
        __syncthreads();
        #pragma unroll
        for (int kk = 0; kk < 16; kk++) {
            float a[8];
            *(float4*)&a[0] = *(const float4*)&As[kk][tm];
            *(float4*)&a[4] = *(const float4*)&As[kk][tm + 4];
            unsigned long long b2v[4];
            float bl[8];
            *(float4*)&bl[0] = *(const float4*)&Bs[kk][tn];
            *(float4*)&bl[4] = *(const float4*)&Bs[kk][tn + 4];
            #pragma unroll
            for (int j = 0; j < 4; j++) b2v[j] = pack2(bl[2 * j], bl[2 * j + 1]);
            #pragma unroll
            for (int i = 0; i < 8; i++) {
                unsigned long long a2 = pack2(a[i], a[i]);
                #pragma unroll
                for (int j = 0; j < 4; j++) acc[i][j] = fma2(a2, b2v[j], acc[i][j]);
            }
        }
        __syncthreads();
    }

    float aS[8], aD[8];
    #pragma unroll
    for (int j = 0; j < 8; j++) {
        aS[j] = a_src[tn + j];
        aD[j] = a_dst[tn + j];
    }
    #pragma unroll
    for (int i = 0; i < 8; i++) {
        int m = bm + tm + i;
        float o[8];
        #pragma unroll
        for (int j = 0; j < 4; j++) unpack2(acc[i][j], o[2 * j], o[2 * j + 1]);
        if (m < M) {
            float* dst = C + (size_t)m * N + tn;
            *(float4*)dst = *(float4*)&o[0];
            *(float4*)(dst + 4) = *(float4*)&o[4];
        }
        float s = 0.f, dv = 0.f;
        #pragma unroll
        for (int j = 0; j < 8; j++) { s += o[j] * aS[j]; dv += o[j] * aD[j]; }
        #pragma unroll
        for (int o2 = 1; o2 < 8; o2 <<= 1) {
            s  += __shfl_xor_sync(0xFFFFFFFFu, s, o2);
            dv += __shfl_xor_sync(0xFFFFFFFFu, dv, o2);
        }
        if ((tid & 7) == 0 && m < M) {
            es[m] = s;
            ed[m] = dv;
        }
    }
}

// ---------------- layer-1 pull aggregation: warp per (node, head) ----------------
__global__ void agg1_kernel(const int* __restrict__ off, const int* __restrict__ csr,
                            const float* __restrict__ h,
                            const float* __restrict__ es, const float* __restrict__ ed,
                            const float* __restrict__ b1, float* __restrict__ out) {
    int gw = (blockIdx.x * blockDim.x + threadIdx.x) >> 5;
    int lane = threadIdx.x & 31;
    if (gw >= N_NODES * HEADS) return;
    int n = gw >> 2, head = gw & 3;
    int beg = off[n], end = off[n + 1];
    float edn = ed[n * HEADS + head];
    float accx = 0.f, accy = 0.f, zsum = 0.f;
    for (int base = beg; base < end; base += 32) {
        int m = min(32, end - base);
        int sl = 0; float pl = 0.f;
        if (base + lane < end) {
            sl = csr[base + lane];
            float l = es[sl * HEADS + head] + edn;
            l = l > 0.f ? l : 0.2f * l;
            pl = expf(l);
        }
        int j = 0;
        for (; j + 2 <= m; j += 2) {
            int s0 = __shfl_sync(0xFFFFFFFFu, sl, j);
            int s1 = __shfl_sync(0xFFFFFFFFu, sl, j + 1);
            float p0 = __shfl_sync(0xFFFFFFFFu, pl, j);
            float p1 = __shfl_sync(0xFFFFFFFFu, pl, j + 1);
            float2 v0 = *(const float2*)(h + (size_t)s0 * F1 + head * 64 + lane * 2);
            float2 v1 = *(const float2*)(h + (size_t)s1 * F1 + head * 64 + lane * 2);
            zsum += p0 + p1;
            accx += p0 * v0.x + p1 * v1.x;
            accy += p0 * v0.y + p1 * v1.y;
        }
        if (j < m) {
            int s0 = __shfl_sync(0xFFFFFFFFu, sl, j);
            float p0 = __shfl_sync(0xFFFFFFFFu, pl, j);
            float2 v0 = *(const float2*)(h + (size_t)s0 * F1 + head * 64 + lane * 2);
            zsum += p0;
            accx += p0 * v0.x;
            accy += p0 * v0.y;
        }
    }
    float inv = 1.f / zsum;
    int c = head * 64 + lane * 2;
    float o0 = accx * inv + b1[c];
    float o1 = accy * inv + b1[c + 1];
    o0 = o0 > 0.f ? o0 : expm1f(o0);
    o1 = o1 > 0.f ? o1 : expm1f(o1);
    float2 r; r.x = o0; r.y = o1;
    *(float2*)(out + (size_t)n * F1 + c) = r;
}

// ---------------- layer-2 pull aggregation: warp per node ----------------
__global__ void agg2_kernel(const int* __restrict__ off, const int* __restrict__ csr,
                            const float* __restrict__ h2,
                            const float* __restrict__ es, const float* __restrict__ ed,
                            const float* __restrict__ b2, float* __restrict__ out) {
    int n = (blockIdx.x * blockDim.x + threadIdx.x) >> 5;
    int lane = threadIdx.x & 31;
    if (n >= N_NODES) return;
    int beg = off[n], end = off[n + 1];
    float edn = ed[n];
    float accx = 0.f, accy = 0.f, zsum = 0.f;
    for (int base = beg; base < end; base += 32) {
        int m = min(32, end - base);
        int sl = 0; float pl = 0.f;
        if (base + lane < end) {
            sl = csr[base + lane];
            float l = es[sl] + edn;
            l = l > 0.f ? l : 0.2f * l;
            pl = expf(l);
        }
        int j = 0;
        for (; j + 2 <= m; j += 2) {
            int s0 = __shfl_sync(0xFFFFFFFFu, sl, j);
            int s1 = __shfl_sync(0xFFFFFFFFu, sl, j + 1);
            float p0 = __shfl_sync(0xFFFFFFFFu, pl, j);
            float p1 = __shfl_sync(0xFFFFFFFFu, pl, j + 1);
            float2 v0 = *(const float2*)(h2 + (size_t)s0 * OUT_C + lane * 2);
            float2 v1 = *(const float2*)(h2 + (size_t)s1 * OUT_C + lane * 2);
            zsum += p0 + p1;
            accx += p0 * v0.x + p1 * v1.x;
            accy += p0 * v0.y + p1 * v1.y;
        }
        if (j < m) {
            int s0 = __shfl_sync(0xFFFFFFFFu, sl, j);
            float p0 = __shfl_sync(0xFFFFFFFFu, pl, j);
            float2 v0 = *(const float2*)(h2 + (size_t)s0 * OUT_C + lane * 2);
            zsum += p0;
            accx += p0 * v0.x;
            accy += p0 * v0.y;
        }
    }
    float inv = 1.f / zsum;
    float2 r;
    r.x = accx * inv + b2[lane * 2];
    r.y = accy * inv + b2[lane * 2 + 1];
    *(float2*)(out + (size_t)n * OUT_C + lane * 2) = r;
}

extern "C" void kernel_launch(void* const* d_in, const int* in_sizes, int n_in,
                              void* d_out, int out_size) {
    const float* x    = (const float*)d_in[0];
    const int*   ei   = (const int*)d_in[1];
    const float* W1   = (const float*)d_in[2];
    const float* a1s  = (const float*)d_in[3];
    const float* a1d  = (const float*)d_in[4];
    const float* b1   = (const float*)d_in[5];
    const float* W2   = (const float*)d_in[6];
    const float* a2s  = (const float*)d_in[7];
    const float* a2d  = (const float*)d_in[8];
    const float* b2   = (const float*)d_in[9];
    float* out = (float*)d_out;

    float *h1, *out1, *h2, *e1s, *e1d, *e2s, *e2d;
    int *cnt, *off, *rank, *csr;
    __nv_bfloat16 *xh, *xl, *wh, *wl;
    cudaGetSymbolAddress((void**)&h1,  g_h1);
    cudaGetSymbolAddress((void**)&out1, g_out1);
    cudaGetSymbolAddress((void**)&h2,  g_h2);
    cudaGetSymbolAddress((void**)&e1s, g_e1s);
    cudaGetSymbolAddress((void**)&e1d, g_e1d);
    cudaGetSymbolAddress((void**)&e2s, g_e2s);
    cudaGetSymbolAddress((void**)&e2d, g_e2d);
    cudaGetSymbolAddress((void**)&cnt, g_cnt);
    cudaGetSymbolAddress((void**)&off, g_off);
    cudaGetSymbolAddress((void**)&rank, g_rank);
    cudaGetSymbolAddress((void**)&csr, g_csr);
    cudaGetSymbolAddress((void**)&xh, g_xh);
    cudaGetSymbolAddress((void**)&xl, g_xl);
    cudaGetSymbolAddress((void**)&wh, g_wh);
    cudaGetSymbolAddress((void**)&wl, g_wl);

    cudaFuncSetAttribute(gemm1_mma_kernel,
                         cudaFuncAttributeMaxDynamicSharedMemorySize, 2 * STAGE);

    initcnt_kernel<<<(N_NODES + 255) / 256, 256>>>(cnt);                       // 0
    convx_kernel<<<((size_t)N_PAD * IN_C / 4 + 255) / 256, 256>>>(x, xh, xl);  // 1
    convw_kernel<<<(IN_C * F1 + 255) / 256, 256>>>(W1, wh, wl);                // 2

    // ---- Layer 1 GEMM on HMMA (+ fused attention dots), ncu index 3 ----
    {
        dim3 grid(F1 / 128, (N_NODES + 127) / 128);
        gemm1_mma_kernel<<<grid, 256, 2 * STAGE>>>(xh, xl, wh, wl, h1, N_NODES, // 3
                                                   a1s, a1d, e1s, e1d);
    }

    count_kernel<<<(E_EDGES / 4 + 255) / 256, 256>>>(ei, cnt, rank);           // 4
    scan_kernel<<<1, 1024>>>(cnt, off, csr);                                   // 5
    fill_kernel<<<(E_EDGES / 4 + 255) / 256, 256>>>(ei, off, rank, csr);       // 6
    agg1_kernel<<<(N_NODES * HEADS * 32 + 255) / 256, 256>>>(off, csr, h1,     // 7
                                                             e1s, e1d, b1, out1);

    // ---- Layer 2 ----
    {
        dim3 grid(1, (N_NODES + 127) / 128);
        sgemm2_kernel<<<grid, 128>>>(out1, W2, h2, N_NODES, F1,                // 8
                                     a2s, a2d, e2s, e2d);
    }
    agg2_kernel<<<(N_NODES * 32 + 255) / 256, 256>>>(off, csr, h2,             // 9
                                                     e2s, e2d, b2, out);
}

// round 12
// speedup vs baseline: 1.0184x; 1.0184x over previous
#include <cuda_runtime.h>
#include <cuda_bf16.h>
#include <cstdint>

#define N_NODES 20000
#define N_PAD   20096                 // padded rows for OOB-safe cp.async
#define E_EDGES 320000
#define E_TOT   (E_EDGES + N_NODES)
#define IN_C    256
#define HID     64
#define HEADS   4
#define OUT_C   64
#define F1      (HEADS * HID)         // 256

// ---------------- scratch (device globals, no allocs) ----------------
__device__ float g_h1[(size_t)N_NODES * F1];
__device__ float g_out1[(size_t)N_NODES * F1];
__device__ float g_h2[(size_t)N_NODES * OUT_C];
__device__ float g_e1s[N_NODES * HEADS];
__device__ float g_e1d[N_NODES * HEADS];
__device__ float g_e2s[N_NODES];
__device__ float g_e2d[N_NODES];
__device__ int   g_cnt[N_NODES];
__device__ int   g_off[N_NODES + 1];
__device__ int   g_rank[E_EDGES];
__device__ int   g_csr[E_TOT];
__device__ __nv_bfloat16 g_xh[(size_t)N_PAD * IN_C];
__device__ __nv_bfloat16 g_xl[(size_t)N_PAD * IN_C];
__device__ __nv_bfloat16 g_wh[IN_C * F1];   // n-major: [n][k]
__device__ __nv_bfloat16 g_wl[IN_C * F1];

// ================= CSR build =================
__global__ void initcnt_kernel(int* __restrict__ cnt) {
    int i = blockIdx.x * blockDim.x + threadIdx.x;
    if (i < N_NODES) cnt[i] = 0;
}
__global__ void count_kernel(const int* __restrict__ ei, int* __restrict__ cnt,
                             int* __restrict__ rank) {
    int e = (blockIdx.x * blockDim.x + threadIdx.x) * 4;
    if (e >= E_EDGES) return;
    int4 d4 = *(const int4*)(ei + E_EDGES + e);
    int4 r4;
    r4.x = atomicAdd(&cnt[d4.x], 1);
    r4.y = atomicAdd(&cnt[d4.y], 1);
    r4.z = atomicAdd(&cnt[d4.z], 1);
    r4.w = atomicAdd(&cnt[d4.w], 1);
    *(int4*)(rank + e) = r4;
}
__global__ void __launch_bounds__(1024) scan_kernel(const int* __restrict__ cnt,
                                                    int* __restrict__ off,
                                                    int* __restrict__ csr) {
    __shared__ int wsum[32];
    const int CH = (N_NODES + 1023) / 1024;   // 20
    int tid = threadIdx.x;
    int lane = tid & 31, warp = tid >> 5;
    int base = tid * CH;
    int local[CH];
    int sum = 0;
    #pragma unroll
    for (int i = 0; i < CH; i++) {
        int idx = base + i;
        int v = idx < N_NODES ? (cnt[idx] + 1) : 0;
        local[i] = sum;
        sum += v;
    }
    int inc = sum;
    #pragma unroll
    for (int o = 1; o < 32; o <<= 1) {
        int t = __shfl_up_sync(0xFFFFFFFFu, inc, o);
        if (lane >= o) inc += t;
    }
    if (lane == 31) wsum[warp] = inc;
    __syncthreads();
    if (warp == 0) {
        int w = wsum[lane];
        #pragma unroll
        for (int o = 1; o < 32; o <<= 1) {
            int t = __shfl_up_sync(0xFFFFFFFFu, w, o);
            if (lane >= o) w += t;
        }
        wsum[lane] = w;
    }
    __syncthreads();
    int prev = inc - sum + (warp ? wsum[warp - 1] : 0);
    #pragma unroll
    for (int i = 0; i < CH; i++) {
        int idx = base + i;
        if (idx < N_NODES) {
            int v = prev + local[i];
            off[idx] = v;
            csr[v] = idx;   // self-loop at slot 0
        }
    }
    if (tid == 1023) off[N_NODES] = prev + sum;
}
__global__ void fill_kernel(const int* __restrict__ ei, const int* __restrict__ off,
                            const int* __restrict__ rank, int* __restrict__ csr) {
    int e = (blockIdx.x * blockDim.x + threadIdx.x) * 4;
    if (e >= E_EDGES) return;
    int4 s4 = *(const int4*)(ei + e);
    int4 d4 = *(const int4*)(ei + E_EDGES + e);
    int4 r4 = *(const int4*)(rank + e);
    csr[off[d4.x] + 1 + r4.x] = s4.x;
    csr[off[d4.y] + 1 + r4.y] = s4.y;
    csr[off[d4.z] + 1 + r4.z] = s4.z;
    csr[off[d4.w] + 1 + r4.w] = s4.w;
}

// ================= fp32 -> bf16 hi/lo prepass =================
__global__ void convx_kernel(const float* __restrict__ x,
                             __nv_bfloat16* __restrict__ xh,
                             __nv_bfloat16* __restrict__ xl) {
    size_t i = (size_t)(blockIdx.x * blockDim.x + threadIdx.x) * 4;
    if (i >= (size_t)N_PAD * IN_C) return;
    float4 v = make_float4(0.f, 0.f, 0.f, 0.f);
    if (i < (size_t)N_NODES * IN_C) v = *(const float4*)(x + i);
    __nv_bfloat16 h0 = __float2bfloat16(v.x), h1 = __float2bfloat16(v.y);
    __nv_bfloat16 h2 = __float2bfloat16(v.z), h3 = __float2bfloat16(v.w);
    *(__nv_bfloat162*)(xh + i)     = __nv_bfloat162(h0, h1);
    *(__nv_bfloat162*)(xh + i + 2) = __nv_bfloat162(h2, h3);
    *(__nv_bfloat162*)(xl + i) = __nv_bfloat162(
        __float2bfloat16(v.x - __bfloat162float(h0)),
        __float2bfloat16(v.y - __bfloat162float(h1)));
    *(__nv_bfloat162*)(xl + i + 2) = __nv_bfloat162(
        __float2bfloat16(v.z - __bfloat162float(h2)),
        __float2bfloat16(v.w - __bfloat162float(h3)));
}
__global__ void convw_kernel(const float* __restrict__ w,
                             __nv_bfloat16* __restrict__ wh,
                             __nv_bfloat16* __restrict__ wl) {
    int i = blockIdx.x * blockDim.x + threadIdx.x;
    if (i >= IN_C * F1) return;
    int n = i >> 8, k = i & 255;
    float v = w[(size_t)k * F1 + n];
    __nv_bfloat16 h = __float2bfloat16(v);
    wh[i] = h;
    wl[i] = __float2bfloat16(v - __bfloat162float(h));
}

// ---------------- mma / ldmatrix / cp.async helpers ----------------
__device__ __forceinline__ void mma_bf16(float* d, const uint32_t* a,
                                         const uint32_t* b, const float* c) {
    asm volatile(
        "mma.sync.aligned.m16n8k16.row.col.f32.bf16.bf16.f32 "
        "{%0,%1,%2,%3}, {%4,%5,%6,%7}, {%8,%9}, {%10,%11,%12,%13};"
        : "=f"(d[0]), "=f"(d[1]), "=f"(d[2]), "=f"(d[3])
        : "r"(a[0]), "r"(a[1]), "r"(a[2]), "r"(a[3]),
          "r"(b[0]), "r"(b[1]),
          "f"(c[0]), "f"(c[1]), "f"(c[2]), "f"(c[3]));
}
__device__ __forceinline__ void ldm_x4(uint32_t* r, uint32_t addr) {
    asm volatile("ldmatrix.sync.aligned.m8n8.x4.shared.b16 {%0,%1,%2,%3}, [%4];"
                 : "=r"(r[0]), "=r"(r[1]), "=r"(r[2]), "=r"(r[3]) : "r"(addr));
}
__device__ __forceinline__ uint32_t smem_u32(const void* p) {
    uint32_t a;
    asm("{ .reg .u64 t; cvta.to.shared.u64 t, %1; cvt.u32.u64 %0, t; }" : "=r"(a) : "l"(p));
    return a;
}
__device__ __forceinline__ void cp16(uint32_t s, const void* g) {
    asm volatile("cp.async.cg.shared.global [%0], [%1], 16;" :: "r"(s), "l"(g) : "memory");
}
#define CP_COMMIT() asm volatile("cp.async.commit_group;" ::: "memory")

// ---------- layer-1 GEMM: HMMA, double-buffered cp.async, pre-converted bf16 ----------
#define ASTRB 80                     // bytes per 32-k row (padded for ldmatrix banks)
#define ARR   (128 * ASTRB)          // 10240 per array
#define STAGE (4 * ARR)              // Ah, Al, Bh, Bl
__global__ void __launch_bounds__(256, 2)
gemm1_mma_kernel(const __nv_bfloat16* __restrict__ Xh, const __nv_bfloat16* __restrict__ Xl,
                 const __nv_bfloat16* __restrict__ Wh, const __nv_bfloat16* __restrict__ Wl,
                 float* __restrict__ C, int M,
                 const float* __restrict__ a_src, const float* __restrict__ a_dst,
                 float* __restrict__ es, float* __restrict__ ed) {
    extern __shared__ char smem[];
    __shared__ float AS[128], AD[128];

    const int tid = threadIdx.x;
    const int w = tid >> 5, lane = tid & 31;
    const int q = lane & 3, r = lane >> 2;
    const int bm = blockIdx.y * 128;
    const int bn = blockIdx.x * 128;
    const int wrow = w * 16;

    if (tid < 128) {
        AS[tid] = a_src[bn + tid];
        AD[tid] = a_dst[bn + tid];
    }
    const uint32_t sbase = smem_u32(smem);

    // per-thread cp.async assignment: row = tid>>1, 32B half = tid&1
    const int lrow = tid >> 1;
    const int lce = (tid & 1) * 16;                 // bf16 elem offset in 32-k row
    const size_t gaA = (size_t)(bm + lrow) * IN_C + lce;
    const size_t gaB = (size_t)(bn + lrow) * IN_C + lce;
    const uint32_t saoff = (uint32_t)(lrow * ASTRB + lce * 2);

    // ldmatrix lane addresses
    const int ln  = lane & 7;
    const int sel = lane >> 3;
    const uint32_t a_off = (uint32_t)((wrow + ln + (sel & 1) * 8) * ASTRB + (sel >> 1) * 16);
    const uint32_t b_off = (uint32_t)(((sel >> 1) * 8 + ln) * ASTRB + (sel & 1) * 16);

    float acc[16][4];
    #pragma unroll
    for (int t = 0; t < 16; t++)
        #pragma unroll
        for (int j = 0; j < 4; j++) acc[t][j] = 0.f;

    // ---- issue stage loads for chunk kc into stage s ----
    auto issue = [&](int kc, int s) {
        const int k0 = kc * 32;
        const uint32_t st = sbase + s * STAGE;
        uint32_t sa = st + saoff;
        cp16(sa,            Xh + gaA + k0);
        cp16(sa + 16,       Xh + gaA + k0 + 8);
        cp16(sa + ARR,      Xl + gaA + k0);
        cp16(sa + ARR + 16, Xl + gaA + k0 + 8);
        sa += 2 * ARR;
        cp16(sa,            Wh + gaB + k0);
        cp16(sa + 16,       Wh + gaB + k0 + 8);
        cp16(sa + ARR,      Wl + gaB + k0);
        cp16(sa + ARR + 16, Wl + gaB + k0 + 8);
    };

    issue(0, 0); CP_COMMIT();
    issue(1, 1); CP_COMMIT();

    for (int kc = 0; kc < 8; kc++) {
        const int s = kc & 1;
        if (kc < 7) asm volatile("cp.async.wait_group 1;" ::: "memory");
        else        asm volatile("cp.async.wait_group 0;" ::: "memory");
        __syncthreads();
        const uint32_t st = sbase + s * STAGE;
        #pragma unroll
        for (int ks = 0; ks < 2; ks++) {
            const uint32_t koff = (uint32_t)(ks * 32);   // 16 elems * 2B
            uint32_t ah[4], al[4];
            ldm_x4(ah, st + a_off + koff);
            ldm_x4(al, st + ARR + a_off + koff);
            #pragma unroll
            for (int tp = 0; tp < 8; tp++) {
                const int t = tp * 2;
                uint32_t bh4[4], bl4[4];
                const uint32_t ba = st + 2 * ARR + b_off + koff + (uint32_t)t * (8 * ASTRB);
                ldm_x4(bh4, ba);
                ldm_x4(bl4, ba + ARR);
                mma_bf16(acc[t],     ah, &bh4[0], acc[t]);
                mma_bf16(acc[t],     ah, &bl4[0], acc[t]);
                mma_bf16(acc[t],     al, &bh4[0], acc[t]);
                mma_bf16(acc[t + 1], ah, &bh4[2], acc[t + 1]);
                mma_bf16(acc[t + 1], ah, &bl4[2], acc[t + 1]);
                mma_bf16(acc[t + 1], al, &bh4[2], acc[t + 1]);
            }
        }
        __syncthreads();
        if (kc + 2 < 8) { issue(kc + 2, s); CP_COMMIT(); }
    }

    // ---- epilogue: store C + fused attention dots ----
    int row0 = bm + wrow + r;
    int row1 = row0 + 8;
    float sd0[2] = {0.f, 0.f}, sd1[2] = {0.f, 0.f};
    float dd0[2] = {0.f, 0.f}, dd1[2] = {0.f, 0.f};
    #pragma unroll
    for (int t = 0; t < 16; t++) {
        int c0 = t * 8 + q * 2;
        int hh = t >> 3;
        sd0[hh] += acc[t][0] * AS[c0] + acc[t][1] * AS[c0 + 1];
        dd0[hh] += acc[t][0] * AD[c0] + acc[t][1] * AD[c0 + 1];
        sd1[hh] += acc[t][2] * AS[c0] + acc[t][3] * AS[c0 + 1];
        dd1[hh] += acc[t][2] * AD[c0] + acc[t][3] * AD[c0 + 1];
        if (row0 < M)
            *(float2*)(C + (size_t)row0 * F1 + bn + c0) = make_float2(acc[t][0], acc[t][1]);
        if (row1 < M)
            *(float2*)(C + (size_t)row1 * F1 + bn + c0) = make_float2(acc[t][2], acc[t][3]);
    }
    #pragma unroll
    for (int o = 1; o < 4; o <<= 1) {
        #pragma unroll
        for (int hh = 0; hh < 2; hh++) {
            sd0[hh] += __shfl_xor_sync(0xFFFFFFFFu, sd0[hh], o);
            sd1[hh] += __shfl_xor_sync(0xFFFFFFFFu, sd1[hh], o);
            dd0[hh] += __shfl_xor_sync(0xFFFFFFFFu, dd0[hh], o);
            dd1[hh] += __shfl_xor_sync(0xFFFFFFFFu, dd1[hh], o);
        }
    }
    if (q == 0) {
        int hb = blockIdx.x * 2;
        if (row0 < M) {
            es[row0 * HEADS + hb]     = sd0[0];
            es[row0 * HEADS + hb + 1] = sd0[1];
            ed[row0 * HEADS + hb]     = dd0[0];
            ed[row0 * HEADS + hb + 1] = dd0[1];
        }
        if (row1 < M) {
            es[row1 * HEADS + hb]     = sd1[0];
            es[row1 * HEADS + hb + 1] = sd1[1];
            ed[row1 * HEADS + hb]     = dd1[0];
            ed[row1 * HEADS + hb + 1] = dd1[1];
        }
    }
}

// ---------- layer-2 GEMM (scalar f32x2, BN=64) ----------
__device__ __forceinline__ unsigned long long pack2(float lo, float hi) {
    unsigned long long r;
    asm("mov.b64 %0, {%1, %2};" : "=l"(r) : "f"(lo), "f"(hi));
    return r;
}
__device__ __forceinline__ void unpack2(unsigned long long v, float& lo, float& hi) {
    asm("mov.b64 {%0, %1}, %2;" : "=f"(lo), "=f"(hi) : "l"(v));
}
__device__ __forceinline__ unsigned long long fma2(unsigned long long a,
                                                   unsigned long long b,
                                                   unsigned long long c) {
    unsigned long long d;
    asm("fma.rn.f32x2 %0, %1, %2, %3;" : "=l"(d) : "l"(a), "l"(b), "l"(c));
    return d;
}
__global__ void __launch_bounds__(128)
sgemm2_kernel(const float* __restrict__ A, const float* __restrict__ B,
              float* __restrict__ C, int M, int K,
              const float* __restrict__ a_src, const float* __restrict__ a_dst,
              float* __restrict__ es, float* __restrict__ ed) {
    const int N = 64;
    __shared__ float As[16][132];
    __shared__ float Bs[16][68];
    const int bm = blockIdx.y * 128;
    const int tid = threadIdx.x;
    const int tm = (tid >> 3) * 8;
    const int tn = (tid & 7) * 8;

    unsigned long long acc[8][4];
    #pragma unroll
    for (int i = 0; i < 8; i++)
        #pragma unroll
        for (int j = 0; j < 4; j++) acc[i][j] = 0ull;

    for (int k0 = 0; k0 < K; k0 += 16) {
        {
            int r = tid;
            int row = bm + r;
            #pragma unroll
            for (int cc = 0; cc < 4; cc++) {
                int c = cc * 4;
                float4 v = make_float4(0.f, 0.f, 0.f, 0.f);
                if (row < M) v = *(const float4*)(A + (size_t)row * K + k0 + c);
                As[c + 0][r] = v.x; As[c + 1][r] = v.y;
                As[c + 2][r] = v.z; As[c + 3][r] = v.w;
            }
        }
        {
            int r = tid >> 3;
            int c = (tid & 7) * 8;
            const float* src = B + (size_t)(k0 + r) * N + c;
            *(float4*)&Bs[r][c] = *(const float4*)src;
            *(float4*)&Bs[r][c + 4] = *(const float4*)(src + 4);
        }
        __syncthreads();
        #pragma unroll
        for (int kk = 0; kk < 16; kk++) {
            float a[8];
            *(float4*)&a[0] = *(const float4*)&As[kk][tm];
            *(float4*)&a[4] = *(const float4*)&As[kk][tm + 4];
            unsigned long long b2v[4];
            float bl[8];
            *(float4*)&bl[0] = *(const float4*)&Bs[kk][tn];
            *(float4*)&bl[4] = *(const float4*)&Bs[kk][tn + 4];
            #pragma unroll
            for (int j = 0; j < 4; j++) b2v[j] = pack2(bl[2 * j], bl[2 * j + 1]);
            #pragma unroll
            for (int i = 0; i < 8; i++) {
                unsigned long long a2 = pack2(a[i], a[i]);
                #pragma unroll
                for (int j = 0; j < 4; j++) acc[i][j] = fma2(a2, b2v[j], acc[i][j]);
            }
        }
        __syncthreads();
    }

    float aS[8], aD[8];
    #pragma unroll
    for (int j = 0; j < 8; j++) {
        aS[j] = a_src[tn + j];
        aD[j] = a_dst[tn + j];
    }
    #pragma unroll
    for (int i = 0; i < 8; i++) {
        int m = bm + tm + i;
        float o[8];
        #pragma unroll
        for (int j = 0; j < 4; j++) unpack2(acc[i][j], o[2 * j], o[2 * j + 1]);
        if (m < M) {
            float* dst = C + (size_t)m * N + tn;
            *(float4*)dst = *(float4*)&o[0];
            *(float4*)(dst + 4) = *(float4*)&o[4];
        }
        float s = 0.f, dv = 0.f;
        #pragma unroll
        for (int j = 0; j < 8; j++) { s += o[j] * aS[j]; dv += o[j] * aD[j]; }
        #pragma unroll
        for (int o2 = 1; o2 < 8; o2 <<= 1) {
            s  += __shfl_xor_sync(0xFFFFFFFFu, s, o2);
            dv += __shfl_xor_sync(0xFFFFFFFFu, dv, o2);
        }
        if ((tid & 7) == 0 && m < M) {
            es[m] = s;
            ed[m] = dv;
        }
    }
}

// ---------------- layer-1 pull aggregation: warp per (node, head) ----------------
__global__ void agg1_kernel(const int* __restrict__ off, const int* __restrict__ csr,
                            const float* __restrict__ h,
                            const float* __restrict__ es, const float* __restrict__ ed,
                            const float* __restrict__ b1, float* __restrict__ out) {
    int gw = (blockIdx.x * blockDim.x + threadIdx.x) >> 5;
    int lane = threadIdx.x & 31;
    if (gw >= N_NODES * HEADS) return;
    int n = gw >> 2, head = gw & 3;
    int beg = off[n], end = off[n + 1];
    float edn = ed[n * HEADS + head];
    float accx = 0.f, accy = 0.f, zsum = 0.f;
    for (int base = beg; base < end; base += 32) {
        int m = min(32, end - base);
        int sl = 0; float pl = 0.f;
        if (base + lane < end) {
            sl = csr[base + lane];
            float l = es[sl * HEADS + head] + edn;
            l = l > 0.f ? l : 0.2f * l;
            pl = expf(l);
        }
        int j = 0;
        for (; j + 2 <= m; j += 2) {
            int s0 = __shfl_sync(0xFFFFFFFFu, sl, j);
            int s1 = __shfl_sync(0xFFFFFFFFu, sl, j + 1);
            float p0 = __shfl_sync(0xFFFFFFFFu, pl, j);
            float p1 = __shfl_sync(0xFFFFFFFFu, pl, j + 1);
            float2 v0 = *(const float2*)(h + (size_t)s0 * F1 + head * 64 + lane * 2);
            float2 v1 = *(const float2*)(h + (size_t)s1 * F1 + head * 64 + lane * 2);
            zsum += p0 + p1;
            accx += p0 * v0.x + p1 * v1.x;
            accy += p0 * v0.y + p1 * v1.y;
        }
        if (j < m) {
            int s0 = __shfl_sync(0xFFFFFFFFu, sl, j);
            float p0 = __shfl_sync(0xFFFFFFFFu, pl, j);
            float2 v0 = *(const float2*)(h + (size_t)s0 * F1 + head * 64 + lane * 2);
            zsum += p0;
            accx += p0 * v0.x;
            accy += p0 * v0.y;
        }
    }
    float inv = 1.f / zsum;
    int c = head * 64 + lane * 2;
    float o0 = accx * inv + b1[c];
    float o1 = accy * inv + b1[c + 1];
    o0 = o0 > 0.f ? o0 : expm1f(o0);
    o1 = o1 > 0.f ? o1 : expm1f(o1);
    float2 r; r.x = o0; r.y = o1;
    *(float2*)(out + (size_t)n * F1 + c) = r;
}

// ---------------- layer-2 pull aggregation: warp per node ----------------
__global__ void agg2_kernel(const int* __restrict__ off, const int* __restrict__ csr,
                            const float* __restrict__ h2,
                            const float* __restrict__ es, const float* __restrict__ ed,
                            const float* __restrict__ b2, float* __restrict__ out) {
    int n = (blockIdx.x * blockDim.x + threadIdx.x) >> 5;
    int lane = threadIdx.x & 31;
    if (n >= N_NODES) return;
    int beg = off[n], end = off[n + 1];
    float edn = ed[n];
    float accx = 0.f, accy = 0.f, zsum = 0.f;
    for (int base = beg; base < end; base += 32) {
        int m = min(32, end - base);
        int sl = 0; float pl = 0.f;
        if (base + lane < end) {
            sl = csr[base + lane];
            float l = es[sl] + edn;
            l = l > 0.f ? l : 0.2f * l;
            pl = expf(l);
        }
        int j = 0;
        for (; j + 2 <= m; j += 2) {
            int s0 = __shfl_sync(0xFFFFFFFFu, sl, j);
            int s1 = __shfl_sync(0xFFFFFFFFu, sl, j + 1);
            float p0 = __shfl_sync(0xFFFFFFFFu, pl, j);
            float p1 = __shfl_sync(0xFFFFFFFFu, pl, j + 1);
            float2 v0 = *(const float2*)(h2 + (size_t)s0 * OUT_C + lane * 2);
            float2 v1 = *(const float2*)(h2 + (size_t)s1 * OUT_C + lane * 2);
            zsum += p0 + p1;
            accx += p0 * v0.x + p1 * v1.x;
            accy += p0 * v0.y + p1 * v1.y;
        }
        if (j < m) {
            int s0 = __shfl_sync(0xFFFFFFFFu, sl, j);
            float p0 = __shfl_sync(0xFFFFFFFFu, pl, j);
            float2 v0 = *(const float2*)(h2 + (size_t)s0 * OUT_C + lane * 2);
            zsum += p0;
            accx += p0 * v0.x;
            accy += p0 * v0.y;
        }
    }
    float inv = 1.f / zsum;
    float2 r;
    r.x = accx * inv + b2[lane * 2];
    r.y = accy * inv + b2[lane * 2 + 1];
    *(float2*)(out + (size_t)n * OUT_C + lane * 2) = r;
}

extern "C" void kernel_launch(void* const* d_in, const int* in_sizes, int n_in,
                              void* d_out, int out_size) {
    const float* x    = (const float*)d_in[0];
    const int*   ei   = (const int*)d_in[1];
    const float* W1   = (const float*)d_in[2];
    const float* a1s  = (const float*)d_in[3];
    const float* a1d  = (const float*)d_in[4];
    const float* b1   = (const float*)d_in[5];
    const float* W2   = (const float*)d_in[6];
    const float* a2s  = (const float*)d_in[7];
    const float* a2d  = (const float*)d_in[8];
    const float* b2   = (const float*)d_in[9];
    float* out = (float*)d_out;

    float *h1, *out1, *h2, *e1s, *e1d, *e2s, *e2d;
    int *cnt, *off, *rank, *csr;
    __nv_bfloat16 *xh, *xl, *wh, *wl;
    cudaGetSymbolAddress((void**)&h1,  g_h1);
    cudaGetSymbolAddress((void**)&out1, g_out1);
    cudaGetSymbolAddress((void**)&h2,  g_h2);
    cudaGetSymbolAddress((void**)&e1s, g_e1s);
    cudaGetSymbolAddress((void**)&e1d, g_e1d);
    cudaGetSymbolAddress((void**)&e2s, g_e2s);
    cudaGetSymbolAddress((void**)&e2d, g_e2d);
    cudaGetSymbolAddress((void**)&cnt, g_cnt);
    cudaGetSymbolAddress((void**)&off, g_off);
    cudaGetSymbolAddress((void**)&rank, g_rank);
    cudaGetSymbolAddress((void**)&csr, g_csr);
    cudaGetSymbolAddress((void**)&xh, g_xh);
    cudaGetSymbolAddress((void**)&xl, g_xl);
    cudaGetSymbolAddress((void**)&wh, g_wh);
    cudaGetSymbolAddress((void**)&wl, g_wl);

    cudaFuncSetAttribute(gemm1_mma_kernel,
                         cudaFuncAttributeMaxDynamicSharedMemorySize, 2 * STAGE);

    initcnt_kernel<<<(N_NODES + 255) / 256, 256>>>(cnt);                       // 0
    convx_kernel<<<((size_t)N_PAD * IN_C / 4 + 255) / 256, 256>>>(x, xh, xl);  // 1
    convw_kernel<<<(IN_C * F1 + 255) / 256, 256>>>(W1, wh, wl);                // 2

    // ---- Layer 1 GEMM on HMMA (+ fused attention dots), ncu index 3 ----
    {
        dim3 grid(F1 / 128, (N_NODES + 127) / 128);
        gemm1_mma_kernel<<<grid, 256, 2 * STAGE>>>(xh, xl, wh, wl, h1, N_NODES, // 3
                                                   a1s, a1d, e1s, e1d);
    }

    count_kernel<<<(E_EDGES / 4 + 255) / 256, 256>>>(ei, cnt, rank);           // 4
    scan_kernel<<<1, 1024>>>(cnt, off, csr);                                   // 5
    fill_kernel<<<(E_EDGES / 4 + 255) / 256, 256>>>(ei, off, rank, csr);       // 6
    agg1_kernel<<<(N_NODES * HEADS * 32 + 255) / 256, 256>>>(off, csr, h1,     // 7
                                                             e1s, e1d, b1, out1);

    // ---- Layer 2 ----
    {
        dim3 grid(1, (N_NODES + 127) / 128);
        sgemm2_kernel<<<grid, 128>>>(out1, W2, h2, N_NODES, F1,                // 8
                                     a2s, a2d, e2s, e2d);
    }
    agg2_kernel<<<(N_NODES * 32 + 255) / 256, 256>>>(off, csr, h2,             // 9
                                                     e2s, e2d, b2, out);
}

// round 14
// speedup vs baseline: 1.0296x; 1.0110x over previous
#include <cuda_runtime.h>
#include <cuda_bf16.h>
#include <cuda_fp16.h>
#include <cstdint>

#define N_NODES 20000
#define N_PAD   20096                 // padded rows for OOB-safe cp.async
#define E_EDGES 320000
#define E_TOT   (E_EDGES + N_NODES)
#define IN_C    256
#define HID     64
#define HEADS   4
#define OUT_C   64
#define F1      (HEADS * HID)         // 256

// ---------------- scratch (device globals, no allocs) ----------------
__device__ __half g_h1h[(size_t)N_NODES * F1];   // layer1 features, fp16
__device__ float g_out1[(size_t)N_NODES * F1];
__device__ float g_h2[(size_t)N_NODES * OUT_C];
__device__ float g_e1s[N_NODES * HEADS];
__device__ float g_e1d[N_NODES * HEADS];
__device__ float g_e2s[N_NODES];
__device__ float g_e2d[N_NODES];
__device__ int   g_cnt[N_NODES];
__device__ int   g_off[N_NODES + 1];
__device__ int   g_rank[E_EDGES];
__device__ int   g_csr[E_TOT];
__device__ __nv_bfloat16 g_xh[(size_t)N_PAD * IN_C];
__device__ __nv_bfloat16 g_xl[(size_t)N_PAD * IN_C];
__device__ __nv_bfloat16 g_wh[IN_C * F1];   // n-major: [n][k]
__device__ __nv_bfloat16 g_wl[IN_C * F1];

// ================= CSR build =================
__global__ void initcnt_kernel(int* __restrict__ cnt) {
    int i = blockIdx.x * blockDim.x + threadIdx.x;
    if (i < N_NODES) cnt[i] = 0;
}
__global__ void count_kernel(const int* __restrict__ ei, int* __restrict__ cnt,
                             int* __restrict__ rank) {
    int e = (blockIdx.x * blockDim.x + threadIdx.x) * 4;
    if (e >= E_EDGES) return;
    int4 d4 = *(const int4*)(ei + E_EDGES + e);
    int4 r4;
    r4.x = atomicAdd(&cnt[d4.x], 1);
    r4.y = atomicAdd(&cnt[d4.y], 1);
    r4.z = atomicAdd(&cnt[d4.z], 1);
    r4.w = atomicAdd(&cnt[d4.w], 1);
    *(int4*)(rank + e) = r4;
}
__global__ void __launch_bounds__(1024) scan_kernel(const int* __restrict__ cnt,
                                                    int* __restrict__ off,
                                                    int* __restrict__ csr) {
    __shared__ int wsum[32];
    const int CH = (N_NODES + 1023) / 1024;   // 20
    int tid = threadIdx.x;
    int lane = tid & 31, warp = tid >> 5;
    int base = tid * CH;
    int local[CH];
    int sum = 0;
    #pragma unroll
    for (int i = 0; i < CH; i++) {
        int idx = base + i;
        int v = idx < N_NODES ? (cnt[idx] + 1) : 0;
        local[i] = sum;
        sum += v;
    }
    int inc = sum;
    #pragma unroll
    for (int o = 1; o < 32; o <<= 1) {
        int t = __shfl_up_sync(0xFFFFFFFFu, inc, o);
        if (lane >= o) inc += t;
    }
    if (lane == 31) wsum[warp] = inc;
    __syncthreads();
    if (warp == 0) {
        int w = wsum[lane];
        #pragma unroll
        for (int o = 1; o < 32; o <<= 1) {
            int t = __shfl_up_sync(0xFFFFFFFFu, w, o);
            if (lane >= o) w += t;
        }
        wsum[lane] = w;
    }
    __syncthreads();
    int prev = inc - sum + (warp ? wsum[warp - 1] : 0);
    #pragma unroll
    for (int i = 0; i < CH; i++) {
        int idx = base + i;
        if (idx < N_NODES) {
            int v = prev + local[i];
            off[idx] = v;
            csr[v] = idx;   // self-loop at slot 0
        }
    }
    if (tid == 1023) off[N_NODES] = prev + sum;
}
__global__ void fill_kernel(const int* __restrict__ ei, const int* __restrict__ off,
                            const int* __restrict__ rank, int* __restrict__ csr) {
    int e = (blockIdx.x * blockDim.x + threadIdx.x) * 4;
    if (e >= E_EDGES) return;
    int4 s4 = *(const int4*)(ei + e);
    int4 d4 = *(const int4*)(ei + E_EDGES + e);
    int4 r4 = *(const int4*)(rank + e);
    csr[off[d4.x] + 1 + r4.x] = s4.x;
    csr[off[d4.y] + 1 + r4.y] = s4.y;
    csr[off[d4.z] + 1 + r4.z] = s4.z;
    csr[off[d4.w] + 1 + r4.w] = s4.w;
}

// ================= fp32 -> bf16 hi/lo prepass =================
__global__ void convx_kernel(const float* __restrict__ x,
                             __nv_bfloat16* __restrict__ xh,
                             __nv_bfloat16* __restrict__ xl) {
    size_t i = (size_t)(blockIdx.x * blockDim.x + threadIdx.x) * 4;
    if (i >= (size_t)N_PAD * IN_C) return;
    float4 v = make_float4(0.f, 0.f, 0.f, 0.f);
    if (i < (size_t)N_NODES * IN_C) v = *(const float4*)(x + i);
    __nv_bfloat16 h0 = __float2bfloat16(v.x), h1 = __float2bfloat16(v.y);
    __nv_bfloat16 h2 = __float2bfloat16(v.z), h3 = __float2bfloat16(v.w);
    *(__nv_bfloat162*)(xh + i)     = __nv_bfloat162(h0, h1);
    *(__nv_bfloat162*)(xh + i + 2) = __nv_bfloat162(h2, h3);
    *(__nv_bfloat162*)(xl + i) = __nv_bfloat162(
        __float2bfloat16(v.x - __bfloat162float(h0)),
        __float2bfloat16(v.y - __bfloat162float(h1)));
    *(__nv_bfloat162*)(xl + i + 2) = __nv_bfloat162(
        __float2bfloat16(v.z - __bfloat162float(h2)),
        __float2bfloat16(v.w - __bfloat162float(h3)));
}
__global__ void convw_kernel(const float* __restrict__ w,
                             __nv_bfloat16* __restrict__ wh,
                             __nv_bfloat16* __restrict__ wl) {
    int i = blockIdx.x * blockDim.x + threadIdx.x;
    if (i >= IN_C * F1) return;
    int n = i >> 8, k = i & 255;
    float v = w[(size_t)k * F1 + n];
    __nv_bfloat16 h = __float2bfloat16(v);
    wh[i] = h;
    wl[i] = __float2bfloat16(v - __bfloat162float(h));
}

// ---------------- mma / ldmatrix / cp.async helpers ----------------
__device__ __forceinline__ void mma_bf16(float* d, const uint32_t* a,
                                         const uint32_t* b, const float* c) {
    asm volatile(
        "mma.sync.aligned.m16n8k16.row.col.f32.bf16.bf16.f32 "
        "{%0,%1,%2,%3}, {%4,%5,%6,%7}, {%8,%9}, {%10,%11,%12,%13};"
        : "=f"(d[0]), "=f"(d[1]), "=f"(d[2]), "=f"(d[3])
        : "r"(a[0]), "r"(a[1]), "r"(a[2]), "r"(a[3]),
          "r"(b[0]), "r"(b[1]),
          "f"(c[0]), "f"(c[1]), "f"(c[2]), "f"(c[3]));
}
__device__ __forceinline__ void ldm_x4(uint32_t* r, uint32_t addr) {
    asm volatile("ldmatrix.sync.aligned.m8n8.x4.shared.b16 {%0,%1,%2,%3}, [%4];"
                 : "=r"(r[0]), "=r"(r[1]), "=r"(r[2]), "=r"(r[3]) : "r"(addr));
}
__device__ __forceinline__ uint32_t smem_u32(const void* p) {
    uint32_t a;
    asm("{ .reg .u64 t; cvta.to.shared.u64 t, %1; cvt.u32.u64 %0, t; }" : "=r"(a) : "l"(p));
    return a;
}
__device__ __forceinline__ void cp16(uint32_t s, const void* g) {
    asm volatile("cp.async.cg.shared.global [%0], [%1], 16;" :: "r"(s), "l"(g) : "memory");
}
#define CP_COMMIT() asm volatile("cp.async.commit_group;" ::: "memory")

// ---------- layer-1 GEMM: HMMA, double-buffered cp.async, pre-converted bf16 ----------
#define ASTRB 80                     // bytes per 32-k row (padded for ldmatrix banks)
#define ARR   (128 * ASTRB)          // 10240 per array
#define STAGE (4 * ARR)              // Ah, Al, Bh, Bl
__global__ void __launch_bounds__(256, 2)
gemm1_mma_kernel(const __nv_bfloat16* __restrict__ Xh, const __nv_bfloat16* __restrict__ Xl,
                 const __nv_bfloat16* __restrict__ Wh, const __nv_bfloat16* __restrict__ Wl,
                 __half* __restrict__ Ch, int M,
                 const float* __restrict__ a_src, const float* __restrict__ a_dst,
                 float* __restrict__ es, float* __restrict__ ed) {
    extern __shared__ char smem[];
    __shared__ float AS[128], AD[128];

    const int tid = threadIdx.x;
    const int w = tid >> 5, lane = tid & 31;
    const int q = lane & 3, r = lane >> 2;
    const int bm = blockIdx.y * 128;
    const int bn = blockIdx.x * 128;
    const int wrow = w * 16;

    if (tid < 128) {
        AS[tid] = a_src[bn + tid];
        AD[tid] = a_dst[bn + tid];
    }
    const uint32_t sbase = smem_u32(smem);

    // per-thread cp.async assignment: row = tid>>1, 32B half = tid&1
    const int lrow = tid >> 1;
    const int lce = (tid & 1) * 16;                 // bf16 elem offset in 32-k row
    const size_t gaA = (size_t)(bm + lrow) * IN_C + lce;
    const size_t gaB = (size_t)(bn + lrow) * IN_C + lce;
    const uint32_t saoff = (uint32_t)(lrow * ASTRB + lce * 2);

    // ldmatrix lane addresses
    const int ln  = lane & 7;
    const int sel = lane >> 3;
    const uint32_t a_off = (uint32_t)((wrow + ln + (sel & 1) * 8) * ASTRB + (sel >> 1) * 16);
    const uint32_t b_off = (uint32_t)(((sel >> 1) * 8 + ln) * ASTRB + (sel & 1) * 16);

    float acc[16][4];
    #pragma unroll
    for (int t = 0; t < 16; t++)
        #pragma unroll
        for (int j = 0; j < 4; j++) acc[t][j] = 0.f;

    // ---- issue stage loads for chunk kc into stage s ----
    auto issue = [&](int kc, int s) {
        const int k0 = kc * 32;
        const uint32_t st = sbase + s * STAGE;
        uint32_t sa = st + saoff;
        cp16(sa,            Xh + gaA + k0);
        cp16(sa + 16,       Xh + gaA + k0 + 8);
        cp16(sa + ARR,      Xl + gaA + k0);
        cp16(sa + ARR + 16, Xl + gaA + k0 + 8);
        sa += 2 * ARR;
        cp16(sa,            Wh + gaB + k0);
        cp16(sa + 16,       Wh + gaB + k0 + 8);
        cp16(sa + ARR,      Wl + gaB + k0);
        cp16(sa + ARR + 16, Wl + gaB + k0 + 8);
    };

    issue(0, 0); CP_COMMIT();
    issue(1, 1); CP_COMMIT();

    for (int kc = 0; kc < 8; kc++) {
        const int s = kc & 1;
        if (kc < 7) asm volatile("cp.async.wait_group 1;" ::: "memory");
        else        asm volatile("cp.async.wait_group 0;" ::: "memory");
        __syncthreads();
        const uint32_t st = sbase + s * STAGE;
        #pragma unroll
        for (int ks = 0; ks < 2; ks++) {
            const uint32_t koff = (uint32_t)(ks * 32);   // 16 elems * 2B
            uint32_t ah[4], al[4];
            ldm_x4(ah, st + a_off + koff);
            ldm_x4(al, st + ARR + a_off + koff);
            #pragma unroll
            for (int tp = 0; tp < 8; tp++) {
                const int t = tp * 2;
                uint32_t bh4[4], bl4[4];
                const uint32_t ba = st + 2 * ARR + b_off + koff + (uint32_t)t * (8 * ASTRB);
                ldm_x4(bh4, ba);
                ldm_x4(bl4, ba + ARR);
                mma_bf16(acc[t],     ah, &bh4[0], acc[t]);
                mma_bf16(acc[t],     ah, &bl4[0], acc[t]);
                mma_bf16(acc[t],     al, &bh4[0], acc[t]);
                mma_bf16(acc[t + 1], ah, &bh4[2], acc[t + 1]);
                mma_bf16(acc[t + 1], ah, &bl4[2], acc[t + 1]);
                mma_bf16(acc[t + 1], al, &bh4[2], acc[t + 1]);
            }
        }
        __syncthreads();
        if (kc + 2 < 8) { issue(kc + 2, s); CP_COMMIT(); }
    }

    // ---- epilogue: store h1 as fp16 + fused attention dots (fp32) ----
    int row0 = bm + wrow + r;
    int row1 = row0 + 8;
    float sd0[2] = {0.f, 0.f}, sd1[2] = {0.f, 0.f};
    float dd0[2] = {0.f, 0.f}, dd1[2] = {0.f, 0.f};
    #pragma unroll
    for (int t = 0; t < 16; t++) {
        int c0 = t * 8 + q * 2;
        int hh = t >> 3;
        sd0[hh] += acc[t][0] * AS[c0] + acc[t][1] * AS[c0 + 1];
        dd0[hh] += acc[t][0] * AD[c0] + acc[t][1] * AD[c0 + 1];
        sd1[hh] += acc[t][2] * AS[c0] + acc[t][3] * AS[c0 + 1];
        dd1[hh] += acc[t][2] * AD[c0] + acc[t][3] * AD[c0 + 1];
        if (row0 < M)
            *(__half2*)(Ch + (size_t)row0 * F1 + bn + c0) =
                __floats2half2_rn(acc[t][0], acc[t][1]);
        if (row1 < M)
            *(__half2*)(Ch + (size_t)row1 * F1 + bn + c0) =
                __floats2half2_rn(acc[t][2], acc[t][3]);
    }
    #pragma unroll
    for (int o = 1; o < 4; o <<= 1) {
        #pragma unroll
        for (int hh = 0; hh < 2; hh++) {
            sd0[hh] += __shfl_xor_sync(0xFFFFFFFFu, sd0[hh], o);
            sd1[hh] += __shfl_xor_sync(0xFFFFFFFFu, sd1[hh], o);
            dd0[hh] += __shfl_xor_sync(0xFFFFFFFFu, dd0[hh], o);
            dd1[hh] += __shfl_xor_sync(0xFFFFFFFFu, dd1[hh], o);
        }
    }
    if (q == 0) {
        int hb = blockIdx.x * 2;
        if (row0 < M) {
            es[row0 * HEADS + hb]     = sd0[0];
            es[row0 * HEADS + hb + 1] = sd0[1];
            ed[row0 * HEADS + hb]     = dd0[0];
            ed[row0 * HEADS + hb + 1] = dd0[1];
        }
        if (row1 < M) {
            es[row1 * HEADS + hb]     = sd1[0];
            es[row1 * HEADS + hb + 1] = sd1[1];
            ed[row1 * HEADS + hb]     = dd1[0];
            ed[row1 * HEADS + hb + 1] = dd1[1];
        }
    }
}

// ---------- layer-2 GEMM (scalar f32x2, BN=64) ----------
__device__ __forceinline__ unsigned long long pack2(float lo, float hi) {
    unsigned long long r;
    asm("mov.b64 %0, {%1, %2};" : "=l"(r) : "f"(lo), "f"(hi));
    return r;
}
__device__ __forceinline__ void unpack2(unsigned long long v, float& lo, float& hi) {
    asm("mov.b64 {%0, %1}, %2;" : "=f"(lo), "=f"(hi) : "l"(v));
}
__device__ __forceinline__ unsigned long long fma2(unsigned long long a,
                                                   unsigned long long b,
                                                   unsigned long long c) {
    unsigned long long d;
    asm("fma.rn.f32x2 %0, %1, %2, %3;" : "=l"(d) : "l"(a), "l"(b), "l"(c));
    return d;
}
__global__ void __launch_bounds__(128)
sgemm2_kernel(const float* __restrict__ A, const float* __restrict__ B,
              float* __restrict__ C, int M, int K,
              const float* __restrict__ a_src, const float* __restrict__ a_dst,
              float* __restrict__ es, float* __restrict__ ed) {
    const int N = 64;
    __shared__ float As[16][132];
    __shared__ float Bs[16][68];
    const int bm = blockIdx.y * 128;
    const int tid = threadIdx.x;
    const int tm = (tid >> 3) * 8;
    const int tn = (tid & 7) * 8;

    unsigned long long acc[8][4];
    #pragma unroll
    for (int i = 0; i < 8; i++)
        #pragma unroll
        for (int j = 0; j < 4; j++) acc[i][j] = 0ull;

    for (int k0 = 0; k0 < K; k0 += 16) {
        {
            int r = tid;
            int row = bm + r;
            #pragma unroll
            for (int cc = 0; cc < 4; cc++) {
                int c = cc * 4;
                float4 v = make_float4(0.f, 0.f, 0.f, 0.f);
                if (row < M) v = *(const float4*)(A + (size_t)row * K + k0 + c);
                As[c + 0][r] = v.x; As[c + 1][r] = v.y;
                As[c + 2][r] = v.z; As[c + 3][r] = v.w;
            }
        }
        {
            int r = tid >> 3;
            int c = (tid & 7) * 8;
            const float* src = B + (size_t)(k0 + r) * N + c;
            *(float4*)&Bs[r][c] = *(const float4*)src;
            *(float4*)&Bs[r][c + 4] = *(const float4*)(src + 4);
        }
        __syncthreads();
        #pragma unroll
        for (int kk = 0; kk < 16; kk++) {
            float a[8];
            *(float4*)&a[0] = *(const float4*)&As[kk][tm];
            *(float4*)&a[4] = *(const float4*)&As[kk][tm + 4];
            unsigned long long b2v[4];
            float bl[8];
            *(float4*)&bl[0] = *(const float4*)&Bs[kk][tn];
            *(float4*)&bl[4] = *(const float4*)&Bs[kk][tn + 4];
            #pragma unroll
            for (int j = 0; j < 4; j++) b2v[j] = pack2(bl[2 * j], bl[2 * j + 1]);
            #pragma unroll
            for (int i = 0; i < 8; i++) {
                unsigned long long a2 = pack2(a[i], a[i]);
                #pragma unroll
                for (int j = 0; j < 4; j++) acc[i][j] = fma2(a2, b2v[j], acc[i][j]);
            }
        }
        __syncthreads();
    }

    float aS[8], aD[8];
    #pragma unroll
    for (int j = 0; j < 8; j++) {
        aS[j] = a_src[tn + j];
        aD[j] = a_dst[tn + j];
    }
    #pragma unroll
    for (int i = 0; i < 8; i++) {
        int m = bm + tm + i;
        float o[8];
        #pragma unroll
        for (int j = 0; j < 4; j++) unpack2(acc[i][j], o[2 * j], o[2 * j + 1]);
        if (m < M) {
            float* dst = C + (size_t)m * N + tn;
            *(float4*)dst = *(float4*)&o[0];
            *(float4*)(dst + 4) = *(float4*)&o[4];
        }
        float s = 0.f, dv = 0.f;
        #pragma unroll
        for (int j = 0; j < 8; j++) { s += o[j] * aS[j]; dv += o[j] * aD[j]; }
        #pragma unroll
        for (int o2 = 1; o2 < 8; o2 <<= 1) {
            s  += __shfl_xor_sync(0xFFFFFFFFu, s, o2);
            dv += __shfl_xor_sync(0xFFFFFFFFu, dv, o2);
        }
        if ((tid & 7) == 0 && m < M) {
            es[m] = s;
            ed[m] = dv;
        }
    }
}

// ---------------- layer-1 pull aggregation: warp per (node, head), fp16 gathers ----------------
__global__ void agg1_kernel(const int* __restrict__ off, const int* __restrict__ csr,
                            const __half* __restrict__ hh16,
                            const float* __restrict__ es, const float* __restrict__ ed,
                            const float* __restrict__ b1, float* __restrict__ out) {
    int gw = (blockIdx.x * blockDim.x + threadIdx.x) >> 5;
    int lane = threadIdx.x & 31;
    if (gw >= N_NODES * HEADS) return;
    int n = gw >> 2, head = gw & 3;
    int beg = off[n], end = off[n + 1];
    float edn = ed[n * HEADS + head];
    float accx = 0.f, accy = 0.f, zsum = 0.f;
    for (int base = beg; base < end; base += 32) {
        int m = min(32, end - base);
        int sl = 0; float pl = 0.f;
        if (base + lane < end) {
            sl = csr[base + lane];
            float l = es[sl * HEADS + head] + edn;
            l = l > 0.f ? l : 0.2f * l;
            pl = expf(l);
        }
        int j = 0;
        for (; j + 2 <= m; j += 2) {
            int s0 = __shfl_sync(0xFFFFFFFFu, sl, j);
            int s1 = __shfl_sync(0xFFFFFFFFu, sl, j + 1);
            float p0 = __shfl_sync(0xFFFFFFFFu, pl, j);
            float p1 = __shfl_sync(0xFFFFFFFFu, pl, j + 1);
            float2 v0 = __half22float2(*(const __half2*)(hh16 + (size_t)s0 * F1 + head * 64 + lane * 2));
            float2 v1 = __half22float2(*(const __half2*)(hh16 + (size_t)s1 * F1 + head * 64 + lane * 2));
            zsum += p0 + p1;
            accx += p0 * v0.x + p1 * v1.x;
            accy += p0 * v0.y + p1 * v1.y;
        }
        if (j < m) {
            int s0 = __shfl_sync(0xFFFFFFFFu, sl, j);
            float p0 = __shfl_sync(0xFFFFFFFFu, pl, j);
            float2 v0 = __half22float2(*(const __half2*)(hh16 + (size_t)s0 * F1 + head * 64 + lane * 2));
            zsum += p0;
            accx += p0 * v0.x;
            accy += p0 * v0.y;
        }
    }
    float inv = 1.f / zsum;
    int c = head * 64 + lane * 2;
    float o0 = accx * inv + b1[c];
    float o1 = accy * inv + b1[c + 1];
    o0 = o0 > 0.f ? o0 : expm1f(o0);
    o1 = o1 > 0.f ? o1 : expm1f(o1);
    float2 r; r.x = o0; r.y = o1;
    *(float2*)(out + (size_t)n * F1 + c) = r;
}

// ---------------- layer-2 pull aggregation: warp per node ----------------
__global__ void agg2_kernel(const int* __restrict__ off, const int* __restrict__ csr,
                            const float* __restrict__ h2,
                            const float* __restrict__ es, const float* __restrict__ ed,
                            const float* __restrict__ b2, float* __restrict__ out) {
    int n = (blockIdx.x * blockDim.x + threadIdx.x) >> 5;
    int lane = threadIdx.x & 31;
    if (n >= N_NODES) return;
    int beg = off[n], end = off[n + 1];
    float edn = ed[n];
    float accx = 0.f, accy = 0.f, zsum = 0.f;
    for (int base = beg; base < end; base += 32) {
        int m = min(32, end - base);
        int sl = 0; float pl = 0.f;
        if (base + lane < end) {
            sl = csr[base + lane];
            float l = es[sl] + edn;
            l = l > 0.f ? l : 0.2f * l;
            pl = expf(l);
        }
        int j = 0;
        for (; j + 2 <= m; j += 2) {
            int s0 = __shfl_sync(0xFFFFFFFFu, sl, j);
            int s1 = __shfl_sync(0xFFFFFFFFu, sl, j + 1);
            float p0 = __shfl_sync(0xFFFFFFFFu, pl, j);
            float p1 = __shfl_sync(0xFFFFFFFFu, pl, j + 1);
            float2 v0 = *(const float2*)(h2 + (size_t)s0 * OUT_C + lane * 2);
            float2 v1 = *(const float2*)(h2 + (size_t)s1 * OUT_C + lane * 2);
            zsum += p0 + p1;
            accx += p0 * v0.x + p1 * v1.x;
            accy += p0 * v0.y + p1 * v1.y;
        }
        if (j < m) {
            int s0 = __shfl_sync(0xFFFFFFFFu, sl, j);
            float p0 = __shfl_sync(0xFFFFFFFFu, pl, j);
            float2 v0 = *(const float2*)(h2 + (size_t)s0 * OUT_C + lane * 2);
            zsum += p0;
            accx += p0 * v0.x;
            accy += p0 * v0.y;
        }
    }
    float inv = 1.f / zsum;
    float2 r;
    r.x = accx * inv + b2[lane * 2];
    r.y = accy * inv + b2[lane * 2 + 1];
    *(float2*)(out + (size_t)n * OUT_C + lane * 2) = r;
}

extern "C" void kernel_launch(void* const* d_in, const int* in_sizes, int n_in,
                              void* d_out, int out_size) {
    const float* x    = (const float*)d_in[0];
    const int*   ei   = (const int*)d_in[1];
    const float* W1   = (const float*)d_in[2];
    const float* a1s  = (const float*)d_in[3];
    const float* a1d  = (const float*)d_in[4];
    const float* b1   = (const float*)d_in[5];
    const float* W2   = (const float*)d_in[6];
    const float* a2s  = (const float*)d_in[7];
    const float* a2d  = (const float*)d_in[8];
    const float* b2   = (const float*)d_in[9];
    float* out = (float*)d_out;

    float *out1, *h2, *e1s, *e1d, *e2s, *e2d;
    int *cnt, *off, *rank, *csr;
    __half *h1h;
    __nv_bfloat16 *xh, *xl, *wh, *wl;
    cudaGetSymbolAddress((void**)&h1h, g_h1h);
    cudaGetSymbolAddress((void**)&out1, g_out1);
    cudaGetSymbolAddress((void**)&h2,  g_h2);
    cudaGetSymbolAddress((void**)&e1s, g_e1s);
    cudaGetSymbolAddress((void**)&e1d, g_e1d);
    cudaGetSymbolAddress((void**)&e2s, g_e2s);
    cudaGetSymbolAddress((void**)&e2d, g_e2d);
    cudaGetSymbolAddress((void**)&cnt, g_cnt);
    cudaGetSymbolAddress((void**)&off, g_off);
    cudaGetSymbolAddress((void**)&rank, g_rank);
    cudaGetSymbolAddress((void**)&csr, g_csr);
    cudaGetSymbolAddress((void**)&xh, g_xh);
    cudaGetSymbolAddress((void**)&xl, g_xl);
    cudaGetSymbolAddress((void**)&wh, g_wh);
    cudaGetSymbolAddress((void**)&wl, g_wl);

    cudaFuncSetAttribute(gemm1_mma_kernel,
                         cudaFuncAttributeMaxDynamicSharedMemorySize, 2 * STAGE);

    initcnt_kernel<<<(N_NODES + 255) / 256, 256>>>(cnt);                       // 0
    convx_kernel<<<((size_t)N_PAD * IN_C / 4 + 255) / 256, 256>>>(x, xh, xl);  // 1
    convw_kernel<<<(IN_C * F1 + 255) / 256, 256>>>(W1, wh, wl);                // 2

    // ---- Layer 1 GEMM on HMMA (+ fused attention dots), ncu index 3 ----
    {
        dim3 grid(F1 / 128, (N_NODES + 127) / 128);
        gemm1_mma_kernel<<<grid, 256, 2 * STAGE>>>(xh, xl, wh, wl, h1h, N_NODES, // 3
                                                   a1s, a1d, e1s, e1d);
    }

    count_kernel<<<(E_EDGES / 4 + 255) / 256, 256>>>(ei, cnt, rank);           // 4
    scan_kernel<<<1, 1024>>>(cnt, off, csr);                                   // 5
    fill_kernel<<<(E_EDGES / 4 + 255) / 256, 256>>>(ei, off, rank, csr);       // 6
    agg1_kernel<<<(N_NODES * HEADS * 32 + 255) / 256, 256>>>(off, csr, h1h,    // 7
                                                             e1s, e1d, b1, out1);

    // ---- Layer 2 ----
    {
        dim3 grid(1, (N_NODES + 127) / 128);
        sgemm2_kernel<<<grid, 128>>>(out1, W2, h2, N_NODES, F1,                // 8
                                     a2s, a2d, e2s, e2d);
    }
    agg2_kernel<<<(N_NODES * 32 + 255) / 256, 256>>>(off, csr, h2,             // 9
                                                     e2s, e2d, b2, out);
}

// round 15
// speedup vs baseline: 1.1586x; 1.1253x over previous
#include <cuda_runtime.h>
#include <cuda_bf16.h>
#include <cuda_fp16.h>
#include <cstdint>

#define N_NODES 20000
#define N_PAD   20096                 // padded rows for OOB-safe cp.async
#define E_EDGES 320000
#define E_TOT   (E_EDGES + N_NODES)
#define IN_C    256
#define HID     64
#define HEADS   4
#define OUT_C   64
#define F1      (HEADS * HID)         // 256

// ---------------- scratch (device globals, no allocs) ----------------
__device__ __half g_h1h[(size_t)N_NODES * F1];          // layer1 features, fp16
__device__ __nv_bfloat16 g_o1h[(size_t)N_PAD * F1];     // layer1 output hi (bf16)
__device__ __nv_bfloat16 g_o1l[(size_t)N_PAD * F1];     // layer1 output lo (bf16)
__device__ float g_h2[(size_t)N_NODES * OUT_C];
__device__ float g_e1s[N_NODES * HEADS];
__device__ float g_e1d[N_NODES * HEADS];
__device__ float g_e2s[N_NODES];
__device__ float g_e2d[N_NODES];
__device__ int   g_cnt[N_NODES];
__device__ int   g_off[N_NODES + 1];
__device__ int   g_rank[E_EDGES];
__device__ int   g_csr[E_TOT];
__device__ __nv_bfloat16 g_xh[(size_t)N_PAD * IN_C];
__device__ __nv_bfloat16 g_xl[(size_t)N_PAD * IN_C];
__device__ __nv_bfloat16 g_wh[IN_C * F1];    // W1^T n-major: [n][k]
__device__ __nv_bfloat16 g_wl[IN_C * F1];
__device__ __nv_bfloat16 g_w2h[OUT_C * F1];  // W2^T n-major: [n][k]
__device__ __nv_bfloat16 g_w2l[OUT_C * F1];

// ================= CSR build =================
__global__ void initcnt_kernel(int* __restrict__ cnt) {
    int i = blockIdx.x * blockDim.x + threadIdx.x;
    if (i < N_NODES) cnt[i] = 0;
}
__global__ void count_kernel(const int* __restrict__ ei, int* __restrict__ cnt,
                             int* __restrict__ rank) {
    int e = (blockIdx.x * blockDim.x + threadIdx.x) * 4;
    if (e >= E_EDGES) return;
    int4 d4 = *(const int4*)(ei + E_EDGES + e);
    int4 r4;
    r4.x = atomicAdd(&cnt[d4.x], 1);
    r4.y = atomicAdd(&cnt[d4.y], 1);
    r4.z = atomicAdd(&cnt[d4.z], 1);
    r4.w = atomicAdd(&cnt[d4.w], 1);
    *(int4*)(rank + e) = r4;
}
__global__ void __launch_bounds__(1024) scan_kernel(const int* __restrict__ cnt,
                                                    int* __restrict__ off,
                                                    int* __restrict__ csr) {
    __shared__ int wsum[32];
    const int CH = (N_NODES + 1023) / 1024;   // 20
    int tid = threadIdx.x;
    int lane = tid & 31, warp = tid >> 5;
    int base = tid * CH;
    int local[CH];
    int sum = 0;
    #pragma unroll
    for (int i = 0; i < CH; i++) {
        int idx = base + i;
        int v = idx < N_NODES ? (cnt[idx] + 1) : 0;
        local[i] = sum;
        sum += v;
    }
    int inc = sum;
    #pragma unroll
    for (int o = 1; o < 32; o <<= 1) {
        int t = __shfl_up_sync(0xFFFFFFFFu, inc, o);
        if (lane >= o) inc += t;
    }
    if (lane == 31) wsum[warp] = inc;
    __syncthreads();
    if (warp == 0) {
        int w = wsum[lane];
        #pragma unroll
        for (int o = 1; o < 32; o <<= 1) {
            int t = __shfl_up_sync(0xFFFFFFFFu, w, o);
            if (lane >= o) w += t;
        }
        wsum[lane] = w;
    }
    __syncthreads();
    int prev = inc - sum + (warp ? wsum[warp - 1] : 0);
    #pragma unroll
    for (int i = 0; i < CH; i++) {
        int idx = base + i;
        if (idx < N_NODES) {
            int v = prev + local[i];
            off[idx] = v;
            csr[v] = idx;   // self-loop at slot 0
        }
    }
    if (tid == 1023) off[N_NODES] = prev + sum;
}
__global__ void fill_kernel(const int* __restrict__ ei, const int* __restrict__ off,
                            const int* __restrict__ rank, int* __restrict__ csr) {
    int e = (blockIdx.x * blockDim.x + threadIdx.x) * 4;
    if (e >= E_EDGES) return;
    int4 s4 = *(const int4*)(ei + e);
    int4 d4 = *(const int4*)(ei + E_EDGES + e);
    int4 r4 = *(const int4*)(rank + e);
    csr[off[d4.x] + 1 + r4.x] = s4.x;
    csr[off[d4.y] + 1 + r4.y] = s4.y;
    csr[off[d4.z] + 1 + r4.z] = s4.z;
    csr[off[d4.w] + 1 + r4.w] = s4.w;
}

// ================= fp32 -> bf16 hi/lo prepass =================
__global__ void convx_kernel(const float* __restrict__ x,
                             __nv_bfloat16* __restrict__ xh,
                             __nv_bfloat16* __restrict__ xl) {
    size_t i = (size_t)(blockIdx.x * blockDim.x + threadIdx.x) * 4;
    if (i >= (size_t)N_PAD * IN_C) return;
    float4 v = make_float4(0.f, 0.f, 0.f, 0.f);
    if (i < (size_t)N_NODES * IN_C) v = *(const float4*)(x + i);
    __nv_bfloat16 h0 = __float2bfloat16(v.x), h1 = __float2bfloat16(v.y);
    __nv_bfloat16 h2 = __float2bfloat16(v.z), h3 = __float2bfloat16(v.w);
    *(__nv_bfloat162*)(xh + i)     = __nv_bfloat162(h0, h1);
    *(__nv_bfloat162*)(xh + i + 2) = __nv_bfloat162(h2, h3);
    *(__nv_bfloat162*)(xl + i) = __nv_bfloat162(
        __float2bfloat16(v.x - __bfloat162float(h0)),
        __float2bfloat16(v.y - __bfloat162float(h1)));
    *(__nv_bfloat162*)(xl + i + 2) = __nv_bfloat162(
        __float2bfloat16(v.z - __bfloat162float(h2)),
        __float2bfloat16(v.w - __bfloat162float(h3)));
}
// converts W1^T (65536) and W2^T (16384) in one grid
__global__ void convw_kernel(const float* __restrict__ w1, const float* __restrict__ w2,
                             __nv_bfloat16* __restrict__ wh, __nv_bfloat16* __restrict__ wl,
                             __nv_bfloat16* __restrict__ w2h, __nv_bfloat16* __restrict__ w2l) {
    int i = blockIdx.x * blockDim.x + threadIdx.x;
    if (i < IN_C * F1) {
        int n = i >> 8, k = i & 255;
        float v = w1[(size_t)k * F1 + n];
        __nv_bfloat16 h = __float2bfloat16(v);
        wh[i] = h;
        wl[i] = __float2bfloat16(v - __bfloat162float(h));
    } else if (i < IN_C * F1 + OUT_C * F1) {
        int j = i - IN_C * F1;
        int n = j >> 8, k = j & 255;
        float v = w2[(size_t)k * OUT_C + n];
        __nv_bfloat16 h = __float2bfloat16(v);
        w2h[j] = h;
        w2l[j] = __float2bfloat16(v - __bfloat162float(h));
    }
}

// ---------------- mma / ldmatrix / cp.async helpers ----------------
__device__ __forceinline__ void mma_bf16(float* d, const uint32_t* a,
                                         const uint32_t* b, const float* c) {
    asm volatile(
        "mma.sync.aligned.m16n8k16.row.col.f32.bf16.bf16.f32 "
        "{%0,%1,%2,%3}, {%4,%5,%6,%7}, {%8,%9}, {%10,%11,%12,%13};"
        : "=f"(d[0]), "=f"(d[1]), "=f"(d[2]), "=f"(d[3])
        : "r"(a[0]), "r"(a[1]), "r"(a[2]), "r"(a[3]),
          "r"(b[0]), "r"(b[1]),
          "f"(c[0]), "f"(c[1]), "f"(c[2]), "f"(c[3]));
}
__device__ __forceinline__ void ldm_x4(uint32_t* r, uint32_t addr) {
    asm volatile("ldmatrix.sync.aligned.m8n8.x4.shared.b16 {%0,%1,%2,%3}, [%4];"
                 : "=r"(r[0]), "=r"(r[1]), "=r"(r[2]), "=r"(r[3]) : "r"(addr));
}
__device__ __forceinline__ uint32_t smem_u32(const void* p) {
    uint32_t a;
    asm("{ .reg .u64 t; cvta.to.shared.u64 t, %1; cvt.u32.u64 %0, t; }" : "=r"(a) : "l"(p));
    return a;
}
__device__ __forceinline__ void cp16(uint32_t s, const void* g) {
    asm volatile("cp.async.cg.shared.global [%0], [%1], 16;" :: "r"(s), "l"(g) : "memory");
}
#define CP_COMMIT() asm volatile("cp.async.commit_group;" ::: "memory")

#define ASTRB 80                     // bytes per 32-k row (padded for ldmatrix banks)
#define ARR   (128 * ASTRB)          // A array bytes (128 rows)
#define STAGE (4 * ARR)              // gemm1 stage: Ah, Al, Bh, Bl (128 rows each)

// ---------- layer-1 GEMM: HMMA, double-buffered cp.async, pre-converted bf16 ----------
__global__ void __launch_bounds__(256, 2)
gemm1_mma_kernel(const __nv_bfloat16* __restrict__ Xh, const __nv_bfloat16* __restrict__ Xl,
                 const __nv_bfloat16* __restrict__ Wh, const __nv_bfloat16* __restrict__ Wl,
                 __half* __restrict__ Ch, int M,
                 const float* __restrict__ a_src, const float* __restrict__ a_dst,
                 float* __restrict__ es, float* __restrict__ ed) {
    extern __shared__ char smem[];
    __shared__ float AS[128], AD[128];

    const int tid = threadIdx.x;
    const int w = tid >> 5, lane = tid & 31;
    const int q = lane & 3, r = lane >> 2;
    const int bm = blockIdx.y * 128;
    const int bn = blockIdx.x * 128;
    const int wrow = w * 16;

    if (tid < 128) {
        AS[tid] = a_src[bn + tid];
        AD[tid] = a_dst[bn + tid];
    }
    const uint32_t sbase = smem_u32(smem);

    const int lrow = tid >> 1;
    const int lce = (tid & 1) * 16;
    const size_t gaA = (size_t)(bm + lrow) * IN_C + lce;
    const size_t gaB = (size_t)(bn + lrow) * IN_C + lce;
    const uint32_t saoff = (uint32_t)(lrow * ASTRB + lce * 2);

    const int ln  = lane & 7;
    const int sel = lane >> 3;
    const uint32_t a_off = (uint32_t)((wrow + ln + (sel & 1) * 8) * ASTRB + (sel >> 1) * 16);
    const uint32_t b_off = (uint32_t)(((sel >> 1) * 8 + ln) * ASTRB + (sel & 1) * 16);

    float acc[16][4];
    #pragma unroll
    for (int t = 0; t < 16; t++)
        #pragma unroll
        for (int j = 0; j < 4; j++) acc[t][j] = 0.f;

    auto issue = [&](int kc, int s) {
        const int k0 = kc * 32;
        const uint32_t st = sbase + s * STAGE;
        uint32_t sa = st + saoff;
        cp16(sa,            Xh + gaA + k0);
        cp16(sa + 16,       Xh + gaA + k0 + 8);
        cp16(sa + ARR,      Xl + gaA + k0);
        cp16(sa + ARR + 16, Xl + gaA + k0 + 8);
        sa += 2 * ARR;
        cp16(sa,            Wh + gaB + k0);
        cp16(sa + 16,       Wh + gaB + k0 + 8);
        cp16(sa + ARR,      Wl + gaB + k0);
        cp16(sa + ARR + 16, Wl + gaB + k0 + 8);
    };

    issue(0, 0); CP_COMMIT();
    issue(1, 1); CP_COMMIT();

    for (int kc = 0; kc < 8; kc++) {
        const int s = kc & 1;
        if (kc < 7) asm volatile("cp.async.wait_group 1;" ::: "memory");
        else        asm volatile("cp.async.wait_group 0;" ::: "memory");
        __syncthreads();
        const uint32_t st = sbase + s * STAGE;
        #pragma unroll
        for (int ks = 0; ks < 2; ks++) {
            const uint32_t koff = (uint32_t)(ks * 32);
            uint32_t ah[4], al[4];
            ldm_x4(ah, st + a_off + koff);
            ldm_x4(al, st + ARR + a_off + koff);
            #pragma unroll
            for (int tp = 0; tp < 8; tp++) {
                const int t = tp * 2;
                uint32_t bh4[4], bl4[4];
                const uint32_t ba = st + 2 * ARR + b_off + koff + (uint32_t)t * (8 * ASTRB);
                ldm_x4(bh4, ba);
                ldm_x4(bl4, ba + ARR);
                mma_bf16(acc[t],     ah, &bh4[0], acc[t]);
                mma_bf16(acc[t],     ah, &bl4[0], acc[t]);
                mma_bf16(acc[t],     al, &bh4[0], acc[t]);
                mma_bf16(acc[t + 1], ah, &bh4[2], acc[t + 1]);
                mma_bf16(acc[t + 1], ah, &bl4[2], acc[t + 1]);
                mma_bf16(acc[t + 1], al, &bh4[2], acc[t + 1]);
            }
        }
        __syncthreads();
        if (kc + 2 < 8) { issue(kc + 2, s); CP_COMMIT(); }
    }

    int row0 = bm + wrow + r;
    int row1 = row0 + 8;
    float sd0[2] = {0.f, 0.f}, sd1[2] = {0.f, 0.f};
    float dd0[2] = {0.f, 0.f}, dd1[2] = {0.f, 0.f};
    #pragma unroll
    for (int t = 0; t < 16; t++) {
        int c0 = t * 8 + q * 2;
        int hh = t >> 3;
        sd0[hh] += acc[t][0] * AS[c0] + acc[t][1] * AS[c0 + 1];
        dd0[hh] += acc[t][0] * AD[c0] + acc[t][1] * AD[c0 + 1];
        sd1[hh] += acc[t][2] * AS[c0] + acc[t][3] * AS[c0 + 1];
        dd1[hh] += acc[t][2] * AD[c0] + acc[t][3] * AD[c0 + 1];
        if (row0 < M)
            *(__half2*)(Ch + (size_t)row0 * F1 + bn + c0) =
                __floats2half2_rn(acc[t][0], acc[t][1]);
        if (row1 < M)
            *(__half2*)(Ch + (size_t)row1 * F1 + bn + c0) =
                __floats2half2_rn(acc[t][2], acc[t][3]);
    }
    #pragma unroll
    for (int o = 1; o < 4; o <<= 1) {
        #pragma unroll
        for (int hh = 0; hh < 2; hh++) {
            sd0[hh] += __shfl_xor_sync(0xFFFFFFFFu, sd0[hh], o);
            sd1[hh] += __shfl_xor_sync(0xFFFFFFFFu, sd1[hh], o);
            dd0[hh] += __shfl_xor_sync(0xFFFFFFFFu, dd0[hh], o);
            dd1[hh] += __shfl_xor_sync(0xFFFFFFFFu, dd1[hh], o);
        }
    }
    if (q == 0) {
        int hb = blockIdx.x * 2;
        if (row0 < M) {
            es[row0 * HEADS + hb]     = sd0[0];
            es[row0 * HEADS + hb + 1] = sd0[1];
            ed[row0 * HEADS + hb]     = dd0[0];
            ed[row0 * HEADS + hb + 1] = dd0[1];
        }
        if (row1 < M) {
            es[row1 * HEADS + hb]     = sd1[0];
            es[row1 * HEADS + hb + 1] = sd1[1];
            ed[row1 * HEADS + hb]     = dd1[0];
            ed[row1 * HEADS + hb + 1] = dd1[1];
        }
    }
}

// ---------- layer-2 GEMM: HMMA, N=64, A = out1 (bf16 hi/lo from agg1) ----------
#define BARR2  (64 * ASTRB)              // B array bytes (64 rows)
#define STAGE2 (2 * ARR + 2 * BARR2)     // Ah, Al, Bh, Bl
__global__ void __launch_bounds__(256, 2)
gemm2_mma_kernel(const __nv_bfloat16* __restrict__ Ahg, const __nv_bfloat16* __restrict__ Alg,
                 const __nv_bfloat16* __restrict__ Wh, const __nv_bfloat16* __restrict__ Wl,
                 float* __restrict__ C, int M,
                 const float* __restrict__ a_src, const float* __restrict__ a_dst,
                 float* __restrict__ es, float* __restrict__ ed) {
    extern __shared__ char smem[];
    __shared__ float AS[64], AD[64];

    const int tid = threadIdx.x;
    const int w = tid >> 5, lane = tid & 31;
    const int q = lane & 3, r = lane >> 2;
    const int bm = blockIdx.y * 128;
    const int wrow = w * 16;

    if (tid < 64) {
        AS[tid] = a_src[tid];
        AD[tid] = a_dst[tid];
    }
    const uint32_t sbase = smem_u32(smem);

    const int lrow = tid >> 1;
    const int lce = (tid & 1) * 16;
    const size_t gaA = (size_t)(bm + lrow) * F1 + lce;
    const uint32_t saoff = (uint32_t)(lrow * ASTRB + lce * 2);
    // B: 64 rows x 2 halves = 128 assignments (tid < 128)
    const int brow = (tid & 127) >> 1;
    const int bce = (tid & 1) * 16;
    const size_t gaB = (size_t)brow * F1 + bce;
    const uint32_t sboff = (uint32_t)(brow * ASTRB + bce * 2);

    const int ln  = lane & 7;
    const int sel = lane >> 3;
    const uint32_t a_off = (uint32_t)((wrow + ln + (sel & 1) * 8) * ASTRB + (sel >> 1) * 16);
    const uint32_t b_off = (uint32_t)(((sel >> 1) * 8 + ln) * ASTRB + (sel & 1) * 16);

    float acc[8][4];
    #pragma unroll
    for (int t = 0; t < 8; t++)
        #pragma unroll
        for (int j = 0; j < 4; j++) acc[t][j] = 0.f;

    auto issue = [&](int kc, int s) {
        const int k0 = kc * 32;
        const uint32_t st = sbase + s * STAGE2;
        uint32_t sa = st + saoff;
        cp16(sa,            Ahg + gaA + k0);
        cp16(sa + 16,       Ahg + gaA + k0 + 8);
        cp16(sa + ARR,      Alg + gaA + k0);
        cp16(sa + ARR + 16, Alg + gaA + k0 + 8);
        if (tid < 128) {
            uint32_t sb = st + 2 * ARR + sboff;
            cp16(sb,             Wh + gaB + k0);
            cp16(sb + 16,        Wh + gaB + k0 + 8);
            cp16(sb + BARR2,      Wl + gaB + k0);
            cp16(sb + BARR2 + 16, Wl + gaB + k0 + 8);
        }
    };

    issue(0, 0); CP_COMMIT();
    issue(1, 1); CP_COMMIT();

    for (int kc = 0; kc < 8; kc++) {
        const int s = kc & 1;
        if (kc < 7) asm volatile("cp.async.wait_group 1;" ::: "memory");
        else        asm volatile("cp.async.wait_group 0;" ::: "memory");
        __syncthreads();
        const uint32_t st = sbase + s * STAGE2;
        #pragma unroll
        for (int ks = 0; ks < 2; ks++) {
            const uint32_t koff = (uint32_t)(ks * 32);
            uint32_t ah[4], al[4];
            ldm_x4(ah, st + a_off + koff);
            ldm_x4(al, st + ARR + a_off + koff);
            #pragma unroll
            for (int tp = 0; tp < 4; tp++) {
                const int t = tp * 2;
                uint32_t bh4[4], bl4[4];
                const uint32_t ba = st + 2 * ARR + b_off + koff + (uint32_t)t * (8 * ASTRB);
                ldm_x4(bh4, ba);
                ldm_x4(bl4, ba + BARR2);
                mma_bf16(acc[t],     ah, &bh4[0], acc[t]);
                mma_bf16(acc[t],     ah, &bl4[0], acc[t]);
                mma_bf16(acc[t],     al, &bh4[0], acc[t]);
                mma_bf16(acc[t + 1], ah, &bh4[2], acc[t + 1]);
                mma_bf16(acc[t + 1], ah, &bl4[2], acc[t + 1]);
                mma_bf16(acc[t + 1], al, &bh4[2], acc[t + 1]);
            }
        }
        __syncthreads();
        if (kc + 2 < 8) { issue(kc + 2, s); CP_COMMIT(); }
    }

    int row0 = bm + wrow + r;
    int row1 = row0 + 8;
    float sd0 = 0.f, sd1 = 0.f, dd0 = 0.f, dd1 = 0.f;
    #pragma unroll
    for (int t = 0; t < 8; t++) {
        int c0 = t * 8 + q * 2;
        sd0 += acc[t][0] * AS[c0] + acc[t][1] * AS[c0 + 1];
        dd0 += acc[t][0] * AD[c0] + acc[t][1] * AD[c0 + 1];
        sd1 += acc[t][2] * AS[c0] + acc[t][3] * AS[c0 + 1];
        dd1 += acc[t][2] * AD[c0] + acc[t][3] * AD[c0 + 1];
        if (row0 < M)
            *(float2*)(C + (size_t)row0 * OUT_C + c0) = make_float2(acc[t][0], acc[t][1]);
        if (row1 < M)
            *(float2*)(C + (size_t)row1 * OUT_C + c0) = make_float2(acc[t][2], acc[t][3]);
    }
    #pragma unroll
    for (int o = 1; o < 4; o <<= 1) {
        sd0 += __shfl_xor_sync(0xFFFFFFFFu, sd0, o);
        sd1 += __shfl_xor_sync(0xFFFFFFFFu, sd1, o);
        dd0 += __shfl_xor_sync(0xFFFFFFFFu, dd0, o);
        dd1 += __shfl_xor_sync(0xFFFFFFFFu, dd1, o);
    }
    if (q == 0) {
        if (row0 < M) { es[row0] = sd0; ed[row0] = dd0; }
        if (row1 < M) { es[row1] = sd1; ed[row1] = dd1; }
    }
}

// ---------------- layer-1 pull aggregation: warp per (node, head), fp16 gathers ----------------
// writes out1 as bf16 hi/lo pairs for the HMMA layer-2 GEMM
__global__ void agg1_kernel(const int* __restrict__ off, const int* __restrict__ csr,
                            const __half* __restrict__ hh16,
                            const float* __restrict__ es, const float* __restrict__ ed,
                            const float* __restrict__ b1,
                            __nv_bfloat16* __restrict__ oh, __nv_bfloat16* __restrict__ ol) {
    int gw = (blockIdx.x * blockDim.x + threadIdx.x) >> 5;
    int lane = threadIdx.x & 31;
    if (gw >= N_NODES * HEADS) return;
    int n = gw >> 2, head = gw & 3;
    int beg = off[n], end = off[n + 1];
    float edn = ed[n * HEADS + head];
    float accx = 0.f, accy = 0.f, zsum = 0.f;
    for (int base = beg; base < end; base += 32) {
        int m = min(32, end - base);
        int sl = 0; float pl = 0.f;
        if (base + lane < end) {
            sl = csr[base + lane];
            float l = es[sl * HEADS + head] + edn;
            l = l > 0.f ? l : 0.2f * l;
            pl = expf(l);
        }
        int j = 0;
        for (; j + 2 <= m; j += 2) {
            int s0 = __shfl_sync(0xFFFFFFFFu, sl, j);
            int s1 = __shfl_sync(0xFFFFFFFFu, sl, j + 1);
            float p0 = __shfl_sync(0xFFFFFFFFu, pl, j);
            float p1 = __shfl_sync(0xFFFFFFFFu, pl, j + 1);
            float2 v0 = __half22float2(*(const __half2*)(hh16 + (size_t)s0 * F1 + head * 64 + lane * 2));
            float2 v1 = __half22float2(*(const __half2*)(hh16 + (size_t)s1 * F1 + head * 64 + lane * 2));
            zsum += p0 + p1;
            accx += p0 * v0.x + p1 * v1.x;
            accy += p0 * v0.y + p1 * v1.y;
        }
        if (j < m) {
            int s0 = __shfl_sync(0xFFFFFFFFu, sl, j);
            float p0 = __shfl_sync(0xFFFFFFFFu, pl, j);
            float2 v0 = __half22float2(*(const __half2*)(hh16 + (size_t)s0 * F1 + head * 64 + lane * 2));
            zsum += p0;
            accx += p0 * v0.x;
            accy += p0 * v0.y;
        }
    }
    float inv = 1.f / zsum;
    int c = head * 64 + lane * 2;
    float o0 = accx * inv + b1[c];
    float o1 = accy * inv + b1[c + 1];
    o0 = o0 > 0.f ? o0 : expm1f(o0);
    o1 = o1 > 0.f ? o1 : expm1f(o1);
    __nv_bfloat16 h0 = __float2bfloat16(o0), h1 = __float2bfloat16(o1);
    __nv_bfloat16 l0 = __float2bfloat16(o0 - __bfloat162float(h0));
    __nv_bfloat16 l1 = __float2bfloat16(o1 - __bfloat162float(h1));
    *(__nv_bfloat162*)(oh + (size_t)n * F1 + c) = __nv_bfloat162(h0, h1);
    *(__nv_bfloat162*)(ol + (size_t)n * F1 + c) = __nv_bfloat162(l0, l1);
}

// ---------------- layer-2 pull aggregation: warp per node ----------------
__global__ void agg2_kernel(const int* __restrict__ off, const int* __restrict__ csr,
                            const float* __restrict__ h2,
                            const float* __restrict__ es, const float* __restrict__ ed,
                            const float* __restrict__ b2, float* __restrict__ out) {
    int n = (blockIdx.x * blockDim.x + threadIdx.x) >> 5;
    int lane = threadIdx.x & 31;
    if (n >= N_NODES) return;
    int beg = off[n], end = off[n + 1];
    float edn = ed[n];
    float accx = 0.f, accy = 0.f, zsum = 0.f;
    for (int base = beg; base < end; base += 32) {
        int m = min(32, end - base);
        int sl = 0; float pl = 0.f;
        if (base + lane < end) {
            sl = csr[base + lane];
            float l = es[sl] + edn;
            l = l > 0.f ? l : 0.2f * l;
            pl = expf(l);
        }
        int j = 0;
        for (; j + 2 <= m; j += 2) {
            int s0 = __shfl_sync(0xFFFFFFFFu, sl, j);
            int s1 = __shfl_sync(0xFFFFFFFFu, sl, j + 1);
            float p0 = __shfl_sync(0xFFFFFFFFu, pl, j);
            float p1 = __shfl_sync(0xFFFFFFFFu, pl, j + 1);
            float2 v0 = *(const float2*)(h2 + (size_t)s0 * OUT_C + lane * 2);
            float2 v1 = *(const float2*)(h2 + (size_t)s1 * OUT_C + lane * 2);
            zsum += p0 + p1;
            accx += p0 * v0.x + p1 * v1.x;
            accy += p0 * v0.y + p1 * v1.y;
        }
        if (j < m) {
            int s0 = __shfl_sync(0xFFFFFFFFu, sl, j);
            float p0 = __shfl_sync(0xFFFFFFFFu, pl, j);
            float2 v0 = *(const float2*)(h2 + (size_t)s0 * OUT_C + lane * 2);
            zsum += p0;
            accx += p0 * v0.x;
            accy += p0 * v0.y;
        }
    }
    float inv = 1.f / zsum;
    float2 r;
    r.x = accx * inv + b2[lane * 2];
    r.y = accy * inv + b2[lane * 2 + 1];
    *(float2*)(out + (size_t)n * OUT_C + lane * 2) = r;
}

extern "C" void kernel_launch(void* const* d_in, const int* in_sizes, int n_in,
                              void* d_out, int out_size) {
    const float* x    = (const float*)d_in[0];
    const int*   ei   = (const int*)d_in[1];
    const float* W1   = (const float*)d_in[2];
    const float* a1s  = (const float*)d_in[3];
    const float* a1d  = (const float*)d_in[4];
    const float* b1   = (const float*)d_in[5];
    const float* W2   = (const float*)d_in[6];
    const float* a2s  = (const float*)d_in[7];
    const float* a2d  = (const float*)d_in[8];
    const float* b2   = (const float*)d_in[9];
    float* out = (float*)d_out;

    float *h2, *e1s, *e1d, *e2s, *e2d;
    int *cnt, *off, *rank, *csr;
    __half *h1h;
    __nv_bfloat16 *o1h, *o1l, *xh, *xl, *wh, *wl, *w2h, *w2l;
    cudaGetSymbolAddress((void**)&h1h, g_h1h);
    cudaGetSymbolAddress((void**)&o1h, g_o1h);
    cudaGetSymbolAddress((void**)&o1l, g_o1l);
    cudaGetSymbolAddress((void**)&h2,  g_h2);
    cudaGetSymbolAddress((void**)&e1s, g_e1s);
    cudaGetSymbolAddress((void**)&e1d, g_e1d);
    cudaGetSymbolAddress((void**)&e2s, g_e2s);
    cudaGetSymbolAddress((void**)&e2d, g_e2d);
    cudaGetSymbolAddress((void**)&cnt, g_cnt);
    cudaGetSymbolAddress((void**)&off, g_off);
    cudaGetSymbolAddress((void**)&rank, g_rank);
    cudaGetSymbolAddress((void**)&csr, g_csr);
    cudaGetSymbolAddress((void**)&xh, g_xh);
    cudaGetSymbolAddress((void**)&xl, g_xl);
    cudaGetSymbolAddress((void**)&wh, g_wh);
    cudaGetSymbolAddress((void**)&wl, g_wl);
    cudaGetSymbolAddress((void**)&w2h, g_w2h);
    cudaGetSymbolAddress((void**)&w2l, g_w2l);

    cudaFuncSetAttribute(gemm1_mma_kernel,
                         cudaFuncAttributeMaxDynamicSharedMemorySize, 2 * STAGE);
    cudaFuncSetAttribute(gemm2_mma_kernel,
                         cudaFuncAttributeMaxDynamicSharedMemorySize, 2 * STAGE2);

    initcnt_kernel<<<(N_NODES + 255) / 256, 256>>>(cnt);                       // 0
    convx_kernel<<<((size_t)N_PAD * IN_C / 4 + 255) / 256, 256>>>(x, xh, xl);  // 1
    convw_kernel<<<(IN_C * F1 + OUT_C * F1 + 255) / 256, 256>>>(               // 2
        W1, W2, wh, wl, w2h, w2l);

    // ---- Layer 1 GEMM on HMMA (+ fused attention dots), ncu index 3 ----
    {
        dim3 grid(F1 / 128, (N_NODES + 127) / 128);
        gemm1_mma_kernel<<<grid, 256, 2 * STAGE>>>(xh, xl, wh, wl, h1h, N_NODES, // 3
                                                   a1s, a1d, e1s, e1d);
    }

    count_kernel<<<(E_EDGES / 4 + 255) / 256, 256>>>(ei, cnt, rank);           // 4
    scan_kernel<<<1, 1024>>>(cnt, off, csr);                                   // 5
    fill_kernel<<<(E_EDGES / 4 + 255) / 256, 256>>>(ei, off, rank, csr);       // 6
    agg1_kernel<<<(N_NODES * HEADS * 32 + 255) / 256, 256>>>(off, csr, h1h,    // 7
                                                             e1s, e1d, b1, o1h, o1l);

    // ---- Layer 2 GEMM on HMMA ----
    {
        dim3 grid(1, (N_NODES + 127) / 128);
        gemm2_mma_kernel<<<grid, 256, 2 * STAGE2>>>(o1h, o1l, w2h, w2l, h2,    // 8
                                                    N_NODES, a2s, a2d, e2s, e2d);
    }
    agg2_kernel<<<(N_NODES * 32 + 255) / 256, 256>>>(off, csr, h2,             // 9
                                                     e2s, e2d, b2, out);
}

// round 16
// speedup vs baseline: 1.3025x; 1.1243x over previous
#include <cuda_runtime.h>
#include <cuda_bf16.h>
#include <cuda_fp16.h>
#include <cstdint>

#define N_NODES 20000
#define N_PAD   20096
#define E_EDGES 320000
#define E_TOT   (E_EDGES + N_NODES)
#define IN_C    256
#define HID     64
#define HEADS   4
#define OUT_C   64
#define F1      (HEADS * HID)         // 256

// ---------------- scratch (device globals, no allocs) ----------------
__device__ __half g_h1h[(size_t)N_NODES * F1];
__device__ __nv_bfloat16 g_o1h[(size_t)N_PAD * F1];
__device__ __nv_bfloat16 g_o1l[(size_t)N_PAD * F1];
__device__ float g_h2[(size_t)N_NODES * OUT_C];
__device__ float g_e1s[N_NODES * HEADS];
__device__ float g_e1d[N_NODES * HEADS];
__device__ float g_e2s[N_NODES];
__device__ float g_e2d[N_NODES];
__device__ int   g_cnt[N_NODES];
__device__ int   g_off[N_NODES + 1];
__device__ int   g_rank[E_EDGES];
__device__ int   g_csr[E_TOT];
__device__ __nv_bfloat16 g_xh[(size_t)N_PAD * IN_C];
__device__ __nv_bfloat16 g_xl[(size_t)N_PAD * IN_C];
__device__ __nv_bfloat16 g_wh[IN_C * F1];
__device__ __nv_bfloat16 g_wl[IN_C * F1];
__device__ __nv_bfloat16 g_w2h[OUT_C * F1];
__device__ __nv_bfloat16 g_w2l[OUT_C * F1];

#define CONVX_BLOCKS (((size_t)N_PAD * IN_C / 4 + 255) / 256)         // 5024
#define CONVW_BLOCKS ((IN_C * F1 + OUT_C * F1 + 255) / 256)           // 320
#define COUNT_BLOCKS ((E_EDGES / 4 + 255) / 256)                      // 313

// ================= fused prepass: convx | convw | count =================
__global__ void prep_kernel(const float* __restrict__ x,
                            __nv_bfloat16* __restrict__ xh, __nv_bfloat16* __restrict__ xl,
                            const float* __restrict__ w1, const float* __restrict__ w2,
                            __nv_bfloat16* __restrict__ wh, __nv_bfloat16* __restrict__ wl,
                            __nv_bfloat16* __restrict__ w2h, __nv_bfloat16* __restrict__ w2l,
                            const int* __restrict__ ei, int* __restrict__ cnt,
                            int* __restrict__ rank) {
    int b = blockIdx.x;
    int tid = threadIdx.x;
    if (b < (int)CONVX_BLOCKS) {
        size_t i = ((size_t)b * 256 + tid) * 4;
        if (i >= (size_t)N_PAD * IN_C) return;
        float4 v = make_float4(0.f, 0.f, 0.f, 0.f);
        if (i < (size_t)N_NODES * IN_C) v = *(const float4*)(x + i);
        __nv_bfloat16 h0 = __float2bfloat16(v.x), h1 = __float2bfloat16(v.y);
        __nv_bfloat16 h2 = __float2bfloat16(v.z), h3 = __float2bfloat16(v.w);
        *(__nv_bfloat162*)(xh + i)     = __nv_bfloat162(h0, h1);
        *(__nv_bfloat162*)(xh + i + 2) = __nv_bfloat162(h2, h3);
        *(__nv_bfloat162*)(xl + i) = __nv_bfloat162(
            __float2bfloat16(v.x - __bfloat162float(h0)),
            __float2bfloat16(v.y - __bfloat162float(h1)));
        *(__nv_bfloat162*)(xl + i + 2) = __nv_bfloat162(
            __float2bfloat16(v.z - __bfloat162float(h2)),
            __float2bfloat16(v.w - __bfloat162float(h3)));
    } else if (b < (int)(CONVX_BLOCKS + CONVW_BLOCKS)) {
        int i = (b - (int)CONVX_BLOCKS) * 256 + tid;
        if (i < IN_C * F1) {
            int n = i >> 8, k = i & 255;
            float v = w1[(size_t)k * F1 + n];
            __nv_bfloat16 h = __float2bfloat16(v);
            wh[i] = h;
            wl[i] = __float2bfloat16(v - __bfloat162float(h));
        } else if (i < IN_C * F1 + OUT_C * F1) {
            int j = i - IN_C * F1;
            int n = j >> 8, k = j & 255;
            float v = w2[(size_t)k * OUT_C + n];
            __nv_bfloat16 h = __float2bfloat16(v);
            w2h[j] = h;
            w2l[j] = __float2bfloat16(v - __bfloat162float(h));
        }
    } else {
        int e = ((b - (int)(CONVX_BLOCKS + CONVW_BLOCKS)) * 256 + tid) * 4;
        if (e >= E_EDGES) return;
        int4 d4 = *(const int4*)(ei + E_EDGES + e);
        int4 r4;
        r4.x = atomicAdd(&cnt[d4.x], 1);
        r4.y = atomicAdd(&cnt[d4.y], 1);
        r4.z = atomicAdd(&cnt[d4.z], 1);
        r4.w = atomicAdd(&cnt[d4.w], 1);
        *(int4*)(rank + e) = r4;
    }
}

// ================= single-block scan =================
__global__ void __launch_bounds__(1024) scan_kernel(const int* __restrict__ cnt,
                                                    int* __restrict__ off,
                                                    int* __restrict__ csr) {
    __shared__ int wsum[32];
    const int CH = (N_NODES + 1023) / 1024;   // 20
    int tid = threadIdx.x;
    int lane = tid & 31, warp = tid >> 5;
    int base = tid * CH;
    int local[CH];
    int sum = 0;
    #pragma unroll
    for (int i = 0; i < CH; i++) {
        int idx = base + i;
        int v = idx < N_NODES ? (cnt[idx] + 1) : 0;
        local[i] = sum;
        sum += v;
    }
    int inc = sum;
    #pragma unroll
    for (int o = 1; o < 32; o <<= 1) {
        int t = __shfl_up_sync(0xFFFFFFFFu, inc, o);
        if (lane >= o) inc += t;
    }
    if (lane == 31) wsum[warp] = inc;
    __syncthreads();
    if (warp == 0) {
        int w = wsum[lane];
        #pragma unroll
        for (int o = 1; o < 32; o <<= 1) {
            int t = __shfl_up_sync(0xFFFFFFFFu, w, o);
            if (lane >= o) w += t;
        }
        wsum[lane] = w;
    }
    __syncthreads();
    int prev = inc - sum + (warp ? wsum[warp - 1] : 0);
    #pragma unroll
    for (int i = 0; i < CH; i++) {
        int idx = base + i;
        if (idx < N_NODES) {
            int v = prev + local[i];
            off[idx] = v;
            csr[v] = idx;   // self-loop at slot 0
        }
    }
    if (tid == 1023) off[N_NODES] = prev + sum;
}

// ---------------- mma / ldmatrix / cp.async helpers ----------------
__device__ __forceinline__ void mma_bf16(float* d, const uint32_t* a,
                                         const uint32_t* b, const float* c) {
    asm volatile(
        "mma.sync.aligned.m16n8k16.row.col.f32.bf16.bf16.f32 "
        "{%0,%1,%2,%3}, {%4,%5,%6,%7}, {%8,%9}, {%10,%11,%12,%13};"
        : "=f"(d[0]), "=f"(d[1]), "=f"(d[2]), "=f"(d[3])
        : "r"(a[0]), "r"(a[1]), "r"(a[2]), "r"(a[3]),
          "r"(b[0]), "r"(b[1]),
          "f"(c[0]), "f"(c[1]), "f"(c[2]), "f"(c[3]));
}
__device__ __forceinline__ void ldm_x4(uint32_t* r, uint32_t addr) {
    asm volatile("ldmatrix.sync.aligned.m8n8.x4.shared.b16 {%0,%1,%2,%3}, [%4];"
                 : "=r"(r[0]), "=r"(r[1]), "=r"(r[2]), "=r"(r[3]) : "r"(addr));
}
__device__ __forceinline__ uint32_t smem_u32(const void* p) {
    uint32_t a;
    asm("{ .reg .u64 t; cvta.to.shared.u64 t, %1; cvt.u32.u64 %0, t; }" : "=r"(a) : "l"(p));
    return a;
}
__device__ __forceinline__ void cp16(uint32_t s, const void* g) {
    asm volatile("cp.async.cg.shared.global [%0], [%1], 16;" :: "r"(s), "l"(g) : "memory");
}
#define CP_COMMIT() asm volatile("cp.async.commit_group;" ::: "memory")

#define ASTRB 80
#define ARR   (128 * ASTRB)
#define STAGE (4 * ARR)
#define GEMM1_BLOCKS 314              // (F1/128) * ceil(N/128) = 2*157
#define FILL_BLOCKS  313

// ---------- fused: layer-1 GEMM (blocks 0..313) | CSR fill (blocks 314..626) ----------
__global__ void __launch_bounds__(256, 2)
gemm1_fill_kernel(const __nv_bfloat16* __restrict__ Xh, const __nv_bfloat16* __restrict__ Xl,
                  const __nv_bfloat16* __restrict__ Wh, const __nv_bfloat16* __restrict__ Wl,
                  __half* __restrict__ Ch, int M,
                  const float* __restrict__ a_src, const float* __restrict__ a_dst,
                  float* __restrict__ es, float* __restrict__ ed,
                  const int* __restrict__ ei, const int* __restrict__ off,
                  const int* __restrict__ rank, int* __restrict__ csr) {
    extern __shared__ char smem[];
    const int tid = threadIdx.x;

    if (blockIdx.x >= GEMM1_BLOCKS) {
        // ---- fill path ----
        int e = ((blockIdx.x - GEMM1_BLOCKS) * 256 + tid) * 4;
        if (e >= E_EDGES) return;
        int4 s4 = *(const int4*)(ei + e);
        int4 d4 = *(const int4*)(ei + E_EDGES + e);
        int4 r4 = *(const int4*)(rank + e);
        csr[off[d4.x] + 1 + r4.x] = s4.x;
        csr[off[d4.y] + 1 + r4.y] = s4.y;
        csr[off[d4.z] + 1 + r4.z] = s4.z;
        csr[off[d4.w] + 1 + r4.w] = s4.w;
        return;
    }

    // ---- gemm path ----
    __shared__ float AS[128], AD[128];
    const int w = tid >> 5, lane = tid & 31;
    const int q = lane & 3, r = lane >> 2;
    const int bm = (blockIdx.x >> 1) * 128;
    const int bn = (blockIdx.x & 1) * 128;
    const int wrow = w * 16;

    if (tid < 128) {
        AS[tid] = a_src[bn + tid];
        AD[tid] = a_dst[bn + tid];
    }
    const uint32_t sbase = smem_u32(smem);

    const int lrow = tid >> 1;
    const int lce = (tid & 1) * 16;
    const size_t gaA = (size_t)(bm + lrow) * IN_C + lce;
    const size_t gaB = (size_t)(bn + lrow) * IN_C + lce;
    const uint32_t saoff = (uint32_t)(lrow * ASTRB + lce * 2);

    const int ln  = lane & 7;
    const int sel = lane >> 3;
    const uint32_t a_off = (uint32_t)((wrow + ln + (sel & 1) * 8) * ASTRB + (sel >> 1) * 16);
    const uint32_t b_off = (uint32_t)(((sel >> 1) * 8 + ln) * ASTRB + (sel & 1) * 16);

    float acc[16][4];
    #pragma unroll
    for (int t = 0; t < 16; t++)
        #pragma unroll
        for (int j = 0; j < 4; j++) acc[t][j] = 0.f;

    auto issue = [&](int kc, int s) {
        const int k0 = kc * 32;
        const uint32_t st = sbase + s * STAGE;
        uint32_t sa = st + saoff;
        cp16(sa,            Xh + gaA + k0);
        cp16(sa + 16,       Xh + gaA + k0 + 8);
        cp16(sa + ARR,      Xl + gaA + k0);
        cp16(sa + ARR + 16, Xl + gaA + k0 + 8);
        sa += 2 * ARR;
        cp16(sa,            Wh + gaB + k0);
        cp16(sa + 16,       Wh + gaB + k0 + 8);
        cp16(sa + ARR,      Wl + gaB + k0);
        cp16(sa + ARR + 16, Wl + gaB + k0 + 8);
    };

    issue(0, 0); CP_COMMIT();
    issue(1, 1); CP_COMMIT();

    for (int kc = 0; kc < 8; kc++) {
        const int s = kc & 1;
        if (kc < 7) asm volatile("cp.async.wait_group 1;" ::: "memory");
        else        asm volatile("cp.async.wait_group 0;" ::: "memory");
        __syncthreads();
        const uint32_t st = sbase + s * STAGE;
        #pragma unroll
        for (int ks = 0; ks < 2; ks++) {
            const uint32_t koff = (uint32_t)(ks * 32);
            uint32_t ah[4], al[4];
            ldm_x4(ah, st + a_off + koff);
            ldm_x4(al, st + ARR + a_off + koff);
            #pragma unroll
            for (int tp = 0; tp < 8; tp++) {
                const int t = tp * 2;
                uint32_t bh4[4], bl4[4];
                const uint32_t ba = st + 2 * ARR + b_off + koff + (uint32_t)t * (8 * ASTRB);
                ldm_x4(bh4, ba);
                ldm_x4(bl4, ba + ARR);
                mma_bf16(acc[t],     ah, &bh4[0], acc[t]);
                mma_bf16(acc[t],     ah, &bl4[0], acc[t]);
                mma_bf16(acc[t],     al, &bh4[0], acc[t]);
                mma_bf16(acc[t + 1], ah, &bh4[2], acc[t + 1]);
                mma_bf16(acc[t + 1], ah, &bl4[2], acc[t + 1]);
                mma_bf16(acc[t + 1], al, &bh4[2], acc[t + 1]);
            }
        }
        __syncthreads();
        if (kc + 2 < 8) { issue(kc + 2, s); CP_COMMIT(); }
    }

    int row0 = bm + wrow + r;
    int row1 = row0 + 8;
    float sd0[2] = {0.f, 0.f}, sd1[2] = {0.f, 0.f};
    float dd0[2] = {0.f, 0.f}, dd1[2] = {0.f, 0.f};
    #pragma unroll
    for (int t = 0; t < 16; t++) {
        int c0 = t * 8 + q * 2;
        int hh = t >> 3;
        sd0[hh] += acc[t][0] * AS[c0] + acc[t][1] * AS[c0 + 1];
        dd0[hh] += acc[t][0] * AD[c0] + acc[t][1] * AD[c0 + 1];
        sd1[hh] += acc[t][2] * AS[c0] + acc[t][3] * AS[c0 + 1];
        dd1[hh] += acc[t][2] * AD[c0] + acc[t][3] * AD[c0 + 1];
        if (row0 < M)
            *(__half2*)(Ch + (size_t)row0 * F1 + bn + c0) =
                __floats2half2_rn(acc[t][0], acc[t][1]);
        if (row1 < M)
            *(__half2*)(Ch + (size_t)row1 * F1 + bn + c0) =
                __floats2half2_rn(acc[t][2], acc[t][3]);
    }
    #pragma unroll
    for (int o = 1; o < 4; o <<= 1) {
        #pragma unroll
        for (int hh = 0; hh < 2; hh++) {
            sd0[hh] += __shfl_xor_sync(0xFFFFFFFFu, sd0[hh], o);
            sd1[hh] += __shfl_xor_sync(0xFFFFFFFFu, sd1[hh], o);
            dd0[hh] += __shfl_xor_sync(0xFFFFFFFFu, dd0[hh], o);
            dd1[hh] += __shfl_xor_sync(0xFFFFFFFFu, dd1[hh], o);
        }
    }
    if (q == 0) {
        int hb = (blockIdx.x & 1) * 2;
        if (row0 < M) {
            es[row0 * HEADS + hb]     = sd0[0];
            es[row0 * HEADS + hb + 1] = sd0[1];
            ed[row0 * HEADS + hb]     = dd0[0];
            ed[row0 * HEADS + hb + 1] = dd0[1];
        }
        if (row1 < M) {
            es[row1 * HEADS + hb]     = sd1[0];
            es[row1 * HEADS + hb + 1] = sd1[1];
            ed[row1 * HEADS + hb]     = dd1[0];
            ed[row1 * HEADS + hb + 1] = dd1[1];
        }
    }
}

// ---------- layer-2 GEMM: HMMA, N=64 ----------
#define BARR2  (64 * ASTRB)
#define STAGE2 (2 * ARR + 2 * BARR2)
__global__ void __launch_bounds__(256, 2)
gemm2_mma_kernel(const __nv_bfloat16* __restrict__ Ahg, const __nv_bfloat16* __restrict__ Alg,
                 const __nv_bfloat16* __restrict__ Wh, const __nv_bfloat16* __restrict__ Wl,
                 float* __restrict__ C, int M,
                 const float* __restrict__ a_src, const float* __restrict__ a_dst,
                 float* __restrict__ es, float* __restrict__ ed) {
    extern __shared__ char smem[];
    __shared__ float AS[64], AD[64];

    const int tid = threadIdx.x;
    const int w = tid >> 5, lane = tid & 31;
    const int q = lane & 3, r = lane >> 2;
    const int bm = blockIdx.y * 128;
    const int wrow = w * 16;

    if (tid < 64) {
        AS[tid] = a_src[tid];
        AD[tid] = a_dst[tid];
    }
    const uint32_t sbase = smem_u32(smem);

    const int lrow = tid >> 1;
    const int lce = (tid & 1) * 16;
    const size_t gaA = (size_t)(bm + lrow) * F1 + lce;
    const uint32_t saoff = (uint32_t)(lrow * ASTRB + lce * 2);
    const int brow = (tid & 127) >> 1;
    const int bce = (tid & 1) * 16;
    const size_t gaB = (size_t)brow * F1 + bce;
    const uint32_t sboff = (uint32_t)(brow * ASTRB + bce * 2);

    const int ln  = lane & 7;
    const int sel = lane >> 3;
    const uint32_t a_off = (uint32_t)((wrow + ln + (sel & 1) * 8) * ASTRB + (sel >> 1) * 16);
    const uint32_t b_off = (uint32_t)(((sel >> 1) * 8 + ln) * ASTRB + (sel & 1) * 16);

    float acc[8][4];
    #pragma unroll
    for (int t = 0; t < 8; t++)
        #pragma unroll
        for (int j = 0; j < 4; j++) acc[t][j] = 0.f;

    auto issue = [&](int kc, int s) {
        const int k0 = kc * 32;
        const uint32_t st = sbase + s * STAGE2;
        uint32_t sa = st + saoff;
        cp16(sa,            Ahg + gaA + k0);
        cp16(sa + 16,       Ahg + gaA + k0 + 8);
        cp16(sa + ARR,      Alg + gaA + k0);
        cp16(sa + ARR + 16, Alg + gaA + k0 + 8);
        if (tid < 128) {
            uint32_t sb = st + 2 * ARR + sboff;
            cp16(sb,              Wh + gaB + k0);
            cp16(sb + 16,         Wh + gaB + k0 + 8);
            cp16(sb + BARR2,      Wl + gaB + k0);
            cp16(sb + BARR2 + 16, Wl + gaB + k0 + 8);
        }
    };

    issue(0, 0); CP_COMMIT();
    issue(1, 1); CP_COMMIT();

    for (int kc = 0; kc < 8; kc++) {
        const int s = kc & 1;
        if (kc < 7) asm volatile("cp.async.wait_group 1;" ::: "memory");
        else        asm volatile("cp.async.wait_group 0;" ::: "memory");
        __syncthreads();
        const uint32_t st = sbase + s * STAGE2;
        #pragma unroll
        for (int ks = 0; ks < 2; ks++) {
            const uint32_t koff = (uint32_t)(ks * 32);
            uint32_t ah[4], al[4];
            ldm_x4(ah, st + a_off + koff);
            ldm_x4(al, st + ARR + a_off + koff);
            #pragma unroll
            for (int tp = 0; tp < 4; tp++) {
                const int t = tp * 2;
                uint32_t bh4[4], bl4[4];
                const uint32_t ba = st + 2 * ARR + b_off + koff + (uint32_t)t * (8 * ASTRB);
                ldm_x4(bh4, ba);
                ldm_x4(bl4, ba + BARR2);
                mma_bf16(acc[t],     ah, &bh4[0], acc[t]);
                mma_bf16(acc[t],     ah, &bl4[0], acc[t]);
                mma_bf16(acc[t],     al, &bh4[0], acc[t]);
                mma_bf16(acc[t + 1], ah, &bh4[2], acc[t + 1]);
                mma_bf16(acc[t + 1], ah, &bl4[2], acc[t + 1]);
                mma_bf16(acc[t + 1], al, &bh4[2], acc[t + 1]);
            }
        }
        __syncthreads();
        if (kc + 2 < 8) { issue(kc + 2, s); CP_COMMIT(); }
    }

    int row0 = bm + wrow + r;
    int row1 = row0 + 8;
    float sd0 = 0.f, sd1 = 0.f, dd0 = 0.f, dd1 = 0.f;
    #pragma unroll
    for (int t = 0; t < 8; t++) {
        int c0 = t * 8 + q * 2;
        sd0 += acc[t][0] * AS[c0] + acc[t][1] * AS[c0 + 1];
        dd0 += acc[t][0] * AD[c0] + acc[t][1] * AD[c0 + 1];
        sd1 += acc[t][2] * AS[c0] + acc[t][3] * AS[c0 + 1];
        dd1 += acc[t][2] * AD[c0] + acc[t][3] * AD[c0 + 1];
        if (row0 < M)
            *(float2*)(C + (size_t)row0 * OUT_C + c0) = make_float2(acc[t][0], acc[t][1]);
        if (row1 < M)
            *(float2*)(C + (size_t)row1 * OUT_C + c0) = make_float2(acc[t][2], acc[t][3]);
    }
    #pragma unroll
    for (int o = 1; o < 4; o <<= 1) {
        sd0 += __shfl_xor_sync(0xFFFFFFFFu, sd0, o);
        sd1 += __shfl_xor_sync(0xFFFFFFFFu, sd1, o);
        dd0 += __shfl_xor_sync(0xFFFFFFFFu, dd0, o);
        dd1 += __shfl_xor_sync(0xFFFFFFFFu, dd1, o);
    }
    if (q == 0) {
        if (row0 < M) { es[row0] = sd0; ed[row0] = dd0; }
        if (row1 < M) { es[row1] = sd1; ed[row1] = dd1; }
    }
}

// ---------------- layer-1 aggregation: warp per node, all 4 heads ----------------
// lane owns 8 channels (uint4 of fp16); per-edge p for all heads via one float4 es load.
__global__ void agg1_kernel(const int* __restrict__ off, const int* __restrict__ csr,
                            const __half* __restrict__ hh16,
                            const float* __restrict__ es, const float* __restrict__ ed,
                            const float* __restrict__ b1,
                            __nv_bfloat16* __restrict__ oh, __nv_bfloat16* __restrict__ ol) {
    int n = (blockIdx.x * blockDim.x + threadIdx.x) >> 5;
    int lane = threadIdx.x & 31;
    if (n >= N_NODES) return;
    const int myh = lane >> 3;
    int beg = off[n], end = off[n + 1];
    float4 edn = *(const float4*)(ed + n * 4);
    float acc[8];
    #pragma unroll
    for (int k = 0; k < 8; k++) acc[k] = 0.f;
    float zsum = 0.f;

    for (int base = beg; base < end; base += 32) {
        int m = min(32, end - base);
        int sl = 0;
        float4 p4 = make_float4(0.f, 0.f, 0.f, 0.f);
        if (base + lane < end) {
            sl = csr[base + lane];
            float4 e4 = *(const float4*)(es + sl * 4);
            float l0 = e4.x + edn.x; l0 = l0 > 0.f ? l0 : 0.2f * l0;
            float l1 = e4.y + edn.y; l1 = l1 > 0.f ? l1 : 0.2f * l1;
            float l2 = e4.z + edn.z; l2 = l2 > 0.f ? l2 : 0.2f * l2;
            float l3 = e4.w + edn.w; l3 = l3 > 0.f ? l3 : 0.2f * l3;
            p4.x = expf(l0); p4.y = expf(l1); p4.z = expf(l2); p4.w = expf(l3);
        }
        for (int j = 0; j < m; j++) {
            int s = __shfl_sync(0xFFFFFFFFu, sl, j);
            float p0 = __shfl_sync(0xFFFFFFFFu, p4.x, j);
            float p1 = __shfl_sync(0xFFFFFFFFu, p4.y, j);
            float p2 = __shfl_sync(0xFFFFFFFFu, p4.z, j);
            float p3 = __shfl_sync(0xFFFFFFFFu, p4.w, j);
            float p = myh == 0 ? p0 : myh == 1 ? p1 : myh == 2 ? p2 : p3;
            zsum += p;
            uint4 hv = *(const uint4*)(hh16 + (size_t)s * F1 + lane * 8);
            float2 f0 = __half22float2(*(__half2*)&hv.x);
            float2 f1 = __half22float2(*(__half2*)&hv.y);
            float2 f2 = __half22float2(*(__half2*)&hv.z);
            float2 f3 = __half22float2(*(__half2*)&hv.w);
            acc[0] += p * f0.x; acc[1] += p * f0.y;
            acc[2] += p * f1.x; acc[3] += p * f1.y;
            acc[4] += p * f2.x; acc[5] += p * f2.y;
            acc[6] += p * f3.x; acc[7] += p * f3.y;
        }
    }
    float inv = 1.f / zsum;
    int c = lane * 8;
    __nv_bfloat16 hs[8], ls[8];
    #pragma unroll
    for (int k = 0; k < 8; k++) {
        float o = acc[k] * inv + b1[c + k];
        o = o > 0.f ? o : expm1f(o);
        hs[k] = __float2bfloat16(o);
        ls[k] = __float2bfloat16(o - __bfloat162float(hs[k]));
    }
    *(uint4*)(oh + (size_t)n * F1 + c) = *(uint4*)hs;
    *(uint4*)(ol + (size_t)n * F1 + c) = *(uint4*)ls;
}

// ---------------- layer-2 pull aggregation: warp per node ----------------
__global__ void agg2_kernel(const int* __restrict__ off, const int* __restrict__ csr,
                            const float* __restrict__ h2,
                            const float* __restrict__ es, const float* __restrict__ ed,
                            const float* __restrict__ b2, float* __restrict__ out) {
    int n = (blockIdx.x * blockDim.x + threadIdx.x) >> 5;
    int lane = threadIdx.x & 31;
    if (n >= N_NODES) return;
    int beg = off[n], end = off[n + 1];
    float edn = ed[n];
    float accx = 0.f, accy = 0.f, zsum = 0.f;
    for (int base = beg; base < end; base += 32) {
        int m = min(32, end - base);
        int sl = 0; float pl = 0.f;
        if (base + lane < end) {
            sl = csr[base + lane];
            float l = es[sl] + edn;
            l = l > 0.f ? l : 0.2f * l;
            pl = expf(l);
        }
        int j = 0;
        for (; j + 2 <= m; j += 2) {
            int s0 = __shfl_sync(0xFFFFFFFFu, sl, j);
            int s1 = __shfl_sync(0xFFFFFFFFu, sl, j + 1);
            float p0 = __shfl_sync(0xFFFFFFFFu, pl, j);
            float p1 = __shfl_sync(0xFFFFFFFFu, pl, j + 1);
            float2 v0 = *(const float2*)(h2 + (size_t)s0 * OUT_C + lane * 2);
            float2 v1 = *(const float2*)(h2 + (size_t)s1 * OUT_C + lane * 2);
            zsum += p0 + p1;
            accx += p0 * v0.x + p1 * v1.x;
            accy += p0 * v0.y + p1 * v1.y;
        }
        if (j < m) {
            int s0 = __shfl_sync(0xFFFFFFFFu, sl, j);
            float p0 = __shfl_sync(0xFFFFFFFFu, pl, j);
            float2 v0 = *(const float2*)(h2 + (size_t)s0 * OUT_C + lane * 2);
            zsum += p0;
            accx += p0 * v0.x;
            accy += p0 * v0.y;
        }
    }
    float inv = 1.f / zsum;
    float2 r;
    r.x = accx * inv + b2[lane * 2];
    r.y = accy * inv + b2[lane * 2 + 1];
    *(float2*)(out + (size_t)n * OUT_C + lane * 2) = r;
}

extern "C" void kernel_launch(void* const* d_in, const int* in_sizes, int n_in,
                              void* d_out, int out_size) {
    const float* x    = (const float*)d_in[0];
    const int*   ei   = (const int*)d_in[1];
    const float* W1   = (const float*)d_in[2];
    const float* a1s  = (const float*)d_in[3];
    const float* a1d  = (const float*)d_in[4];
    const float* b1   = (const float*)d_in[5];
    const float* W2   = (const float*)d_in[6];
    const float* a2s  = (const float*)d_in[7];
    const float* a2d  = (const float*)d_in[8];
    const float* b2   = (const float*)d_in[9];
    float* out = (float*)d_out;

    float *h2, *e1s, *e1d, *e2s, *e2d;
    int *cnt, *off, *rank, *csr;
    __half *h1h;
    __nv_bfloat16 *o1h, *o1l, *xh, *xl, *wh, *wl, *w2h, *w2l;
    cudaGetSymbolAddress((void**)&h1h, g_h1h);
    cudaGetSymbolAddress((void**)&o1h, g_o1h);
    cudaGetSymbolAddress((void**)&o1l, g_o1l);
    cudaGetSymbolAddress((void**)&h2,  g_h2);
    cudaGetSymbolAddress((void**)&e1s, g_e1s);
    cudaGetSymbolAddress((void**)&e1d, g_e1d);
    cudaGetSymbolAddress((void**)&e2s, g_e2s);
    cudaGetSymbolAddress((void**)&e2d, g_e2d);
    cudaGetSymbolAddress((void**)&cnt, g_cnt);
    cudaGetSymbolAddress((void**)&off, g_off);
    cudaGetSymbolAddress((void**)&rank, g_rank);
    cudaGetSymbolAddress((void**)&csr, g_csr);
    cudaGetSymbolAddress((void**)&xh, g_xh);
    cudaGetSymbolAddress((void**)&xl, g_xl);
    cudaGetSymbolAddress((void**)&wh, g_wh);
    cudaGetSymbolAddress((void**)&wl, g_wl);
    cudaGetSymbolAddress((void**)&w2h, g_w2h);
    cudaGetSymbolAddress((void**)&w2l, g_w2l);

    cudaFuncSetAttribute(gemm1_fill_kernel,
                         cudaFuncAttributeMaxDynamicSharedMemorySize, 2 * STAGE);
    cudaFuncSetAttribute(gemm2_mma_kernel,
                         cudaFuncAttributeMaxDynamicSharedMemorySize, 2 * STAGE2);

    cudaMemsetAsync(cnt, 0, N_NODES * sizeof(int));   // memset node, not a kernel

    // launch 0: fused convx | convw | count
    prep_kernel<<<(unsigned)(CONVX_BLOCKS + CONVW_BLOCKS + COUNT_BLOCKS), 256>>>(
        x, xh, xl, W1, W2, wh, wl, w2h, w2l, ei, cnt, rank);

    // launch 1: scan (+ self-loop placement)
    scan_kernel<<<1, 1024>>>(cnt, off, csr);

    // launch 2: fused gemm1 | fill
    gemm1_fill_kernel<<<GEMM1_BLOCKS + FILL_BLOCKS, 256, 2 * STAGE>>>(
        xh, xl, wh, wl, h1h, N_NODES, a1s, a1d, e1s, e1d, ei, off, rank, csr);

    // launch 3: agg1 (profiled by ncu)
    agg1_kernel<<<(N_NODES * 32 + 255) / 256, 256>>>(off, csr, h1h,
                                                     e1s, e1d, b1, o1h, o1l);

    // launch 4: gemm2
    {
        dim3 grid(1, (N_NODES + 127) / 128);
        gemm2_mma_kernel<<<grid, 256, 2 * STAGE2>>>(o1h, o1l, w2h, w2l, h2,
                                                    N_NODES, a2s, a2d, e2s, e2d);
    }
    // launch 5: agg2
    agg2_kernel<<<(N_NODES * 32 + 255) / 256, 256>>>(off, csr, h2,
                                                     e2s, e2d, b2, out);
}

// round 17
// speedup vs baseline: 1.4127x; 1.0846x over previous
#include <cuda_runtime.h>
#include <cuda_bf16.h>
#include <cuda_fp16.h>
#include <cstdint>

#define N_NODES 20000
#define N_PAD   20096
#define E_EDGES 320000
#define E_TOT   (E_EDGES + N_NODES)
#define IN_C    256
#define HID     64
#define HEADS   4
#define OUT_C   64
#define F1      (HEADS * HID)         // 256

// ---------------- scratch (device globals, no allocs) ----------------
__device__ __half g_h1h[(size_t)N_NODES * F1];
__device__ __nv_bfloat16 g_o1h[(size_t)N_PAD * F1];
__device__ __nv_bfloat16 g_o1l[(size_t)N_PAD * F1];
__device__ float g_h2[(size_t)N_NODES * OUT_C];
__device__ float g_e1s[N_NODES * HEADS];
__device__ float g_e1d[N_NODES * HEADS];
__device__ float g_e2s[N_NODES];
__device__ float g_e2d[N_NODES];
__device__ int   g_cnt[N_NODES];
__device__ int   g_off[N_NODES + 1];
__device__ int   g_rank[E_EDGES];
__device__ int   g_csr[E_TOT];
__device__ __nv_bfloat16 g_xh[(size_t)N_PAD * IN_C];
__device__ __nv_bfloat16 g_xl[(size_t)N_PAD * IN_C];
__device__ __nv_bfloat16 g_wh[IN_C * F1];
__device__ __nv_bfloat16 g_wl[IN_C * F1];
__device__ __nv_bfloat16 g_w2h[OUT_C * F1];
__device__ __nv_bfloat16 g_w2l[OUT_C * F1];

#define CONVX_BLOCKS (((size_t)N_PAD * IN_C / 4 + 255) / 256)         // 5024
#define CONVW_BLOCKS ((IN_C * F1 + OUT_C * F1 + 255) / 256)           // 320
#define COUNT_BLOCKS ((E_EDGES / 4 + 255) / 256)                      // 313

// ================= fused prepass: convx | convw | count =================
__global__ void prep_kernel(const float* __restrict__ x,
                            __nv_bfloat16* __restrict__ xh, __nv_bfloat16* __restrict__ xl,
                            const float* __restrict__ w1, const float* __restrict__ w2,
                            __nv_bfloat16* __restrict__ wh, __nv_bfloat16* __restrict__ wl,
                            __nv_bfloat16* __restrict__ w2h, __nv_bfloat16* __restrict__ w2l,
                            const int* __restrict__ ei, int* __restrict__ cnt,
                            int* __restrict__ rank) {
    int b = blockIdx.x;
    int tid = threadIdx.x;
    if (b < (int)CONVX_BLOCKS) {
        size_t i = ((size_t)b * 256 + tid) * 4;
        if (i >= (size_t)N_PAD * IN_C) return;
        float4 v = make_float4(0.f, 0.f, 0.f, 0.f);
        if (i < (size_t)N_NODES * IN_C) v = *(const float4*)(x + i);
        __nv_bfloat16 h0 = __float2bfloat16(v.x), h1 = __float2bfloat16(v.y);
        __nv_bfloat16 h2 = __float2bfloat16(v.z), h3 = __float2bfloat16(v.w);
        *(__nv_bfloat162*)(xh + i)     = __nv_bfloat162(h0, h1);
        *(__nv_bfloat162*)(xh + i + 2) = __nv_bfloat162(h2, h3);
        *(__nv_bfloat162*)(xl + i) = __nv_bfloat162(
            __float2bfloat16(v.x - __bfloat162float(h0)),
            __float2bfloat16(v.y - __bfloat162float(h1)));
        *(__nv_bfloat162*)(xl + i + 2) = __nv_bfloat162(
            __float2bfloat16(v.z - __bfloat162float(h2)),
            __float2bfloat16(v.w - __bfloat162float(h3)));
    } else if (b < (int)(CONVX_BLOCKS + CONVW_BLOCKS)) {
        int i = (b - (int)CONVX_BLOCKS) * 256 + tid;
        if (i < IN_C * F1) {
            int n = i >> 8, k = i & 255;
            float v = w1[(size_t)k * F1 + n];
            __nv_bfloat16 h = __float2bfloat16(v);
            wh[i] = h;
            wl[i] = __float2bfloat16(v - __bfloat162float(h));
        } else if (i < IN_C * F1 + OUT_C * F1) {
            int j = i - IN_C * F1;
            int n = j >> 8, k = j & 255;
            float v = w2[(size_t)k * OUT_C + n];
            __nv_bfloat16 h = __float2bfloat16(v);
            w2h[j] = h;
            w2l[j] = __float2bfloat16(v - __bfloat162float(h));
        }
    } else {
        int e = ((b - (int)(CONVX_BLOCKS + CONVW_BLOCKS)) * 256 + tid) * 4;
        if (e >= E_EDGES) return;
        int4 d4 = *(const int4*)(ei + E_EDGES + e);
        int4 r4;
        r4.x = atomicAdd(&cnt[d4.x], 1);
        r4.y = atomicAdd(&cnt[d4.y], 1);
        r4.z = atomicAdd(&cnt[d4.z], 1);
        r4.w = atomicAdd(&cnt[d4.w], 1);
        *(int4*)(rank + e) = r4;
    }
}

// ================= single-block scan =================
__global__ void __launch_bounds__(1024) scan_kernel(const int* __restrict__ cnt,
                                                    int* __restrict__ off,
                                                    int* __restrict__ csr) {
    __shared__ int wsum[32];
    const int CH = (N_NODES + 1023) / 1024;   // 20
    int tid = threadIdx.x;
    int lane = tid & 31, warp = tid >> 5;
    int base = tid * CH;
    int local[CH];
    int sum = 0;
    #pragma unroll
    for (int i = 0; i < CH; i++) {
        int idx = base + i;
        int v = idx < N_NODES ? (cnt[idx] + 1) : 0;
        local[i] = sum;
        sum += v;
    }
    int inc = sum;
    #pragma unroll
    for (int o = 1; o < 32; o <<= 1) {
        int t = __shfl_up_sync(0xFFFFFFFFu, inc, o);
        if (lane >= o) inc += t;
    }
    if (lane == 31) wsum[warp] = inc;
    __syncthreads();
    if (warp == 0) {
        int w = wsum[lane];
        #pragma unroll
        for (int o = 1; o < 32; o <<= 1) {
            int t = __shfl_up_sync(0xFFFFFFFFu, w, o);
            if (lane >= o) w += t;
        }
        wsum[lane] = w;
    }
    __syncthreads();
    int prev = inc - sum + (warp ? wsum[warp - 1] : 0);
    #pragma unroll
    for (int i = 0; i < CH; i++) {
        int idx = base + i;
        if (idx < N_NODES) {
            int v = prev + local[i];
            off[idx] = v;
            csr[v] = idx;   // self-loop at slot 0
        }
    }
    if (tid == 1023) off[N_NODES] = prev + sum;
}

// ---------------- mma / ldmatrix / cp.async helpers ----------------
__device__ __forceinline__ void mma_bf16(float* d, const uint32_t* a,
                                         const uint32_t* b, const float* c) {
    asm volatile(
        "mma.sync.aligned.m16n8k16.row.col.f32.bf16.bf16.f32 "
        "{%0,%1,%2,%3}, {%4,%5,%6,%7}, {%8,%9}, {%10,%11,%12,%13};"
        : "=f"(d[0]), "=f"(d[1]), "=f"(d[2]), "=f"(d[3])
        : "r"(a[0]), "r"(a[1]), "r"(a[2]), "r"(a[3]),
          "r"(b[0]), "r"(b[1]),
          "f"(c[0]), "f"(c[1]), "f"(c[2]), "f"(c[3]));
}
__device__ __forceinline__ void ldm_x4(uint32_t* r, uint32_t addr) {
    asm volatile("ldmatrix.sync.aligned.m8n8.x4.shared.b16 {%0,%1,%2,%3}, [%4];"
                 : "=r"(r[0]), "=r"(r[1]), "=r"(r[2]), "=r"(r[3]) : "r"(addr));
}
__device__ __forceinline__ uint32_t smem_u32(const void* p) {
    uint32_t a;
    asm("{ .reg .u64 t; cvta.to.shared.u64 t, %1; cvt.u32.u64 %0, t; }" : "=r"(a) : "l"(p));
    return a;
}
__device__ __forceinline__ void cp16(uint32_t s, const void* g) {
    asm volatile("cp.async.cg.shared.global [%0], [%1], 16;" :: "r"(s), "l"(g) : "memory");
}
#define CP_COMMIT() asm volatile("cp.async.commit_group;" ::: "memory")

#define ASTRB 80
#define ARR   (128 * ASTRB)
#define STAGE (4 * ARR)
#define GEMM1_BLOCKS 314
#define FILL_BLOCKS  313

// ---------- fused: layer-1 GEMM (blocks 0..313) | CSR fill (blocks 314..626) ----------
__global__ void __launch_bounds__(256, 2)
gemm1_fill_kernel(const __nv_bfloat16* __restrict__ Xh, const __nv_bfloat16* __restrict__ Xl,
                  const __nv_bfloat16* __restrict__ Wh, const __nv_bfloat16* __restrict__ Wl,
                  __half* __restrict__ Ch, int M,
                  const float* __restrict__ a_src, const float* __restrict__ a_dst,
                  float* __restrict__ es, float* __restrict__ ed,
                  const int* __restrict__ ei, const int* __restrict__ off,
                  const int* __restrict__ rank, int* __restrict__ csr) {
    extern __shared__ char smem[];
    const int tid = threadIdx.x;

    if (blockIdx.x >= GEMM1_BLOCKS) {
        int e = ((blockIdx.x - GEMM1_BLOCKS) * 256 + tid) * 4;
        if (e >= E_EDGES) return;
        int4 s4 = *(const int4*)(ei + e);
        int4 d4 = *(const int4*)(ei + E_EDGES + e);
        int4 r4 = *(const int4*)(rank + e);
        csr[off[d4.x] + 1 + r4.x] = s4.x;
        csr[off[d4.y] + 1 + r4.y] = s4.y;
        csr[off[d4.z] + 1 + r4.z] = s4.z;
        csr[off[d4.w] + 1 + r4.w] = s4.w;
        return;
    }

    __shared__ float AS[128], AD[128];
    const int w = tid >> 5, lane = tid & 31;
    const int q = lane & 3, r = lane >> 2;
    const int bm = (blockIdx.x >> 1) * 128;
    const int bn = (blockIdx.x & 1) * 128;
    const int wrow = w * 16;

    if (tid < 128) {
        AS[tid] = a_src[bn + tid];
        AD[tid] = a_dst[bn + tid];
    }
    const uint32_t sbase = smem_u32(smem);

    const int lrow = tid >> 1;
    const int lce = (tid & 1) * 16;
    const size_t gaA = (size_t)(bm + lrow) * IN_C + lce;
    const size_t gaB = (size_t)(bn + lrow) * IN_C + lce;
    const uint32_t saoff = (uint32_t)(lrow * ASTRB + lce * 2);

    const int ln  = lane & 7;
    const int sel = lane >> 3;
    const uint32_t a_off = (uint32_t)((wrow + ln + (sel & 1) * 8) * ASTRB + (sel >> 1) * 16);
    const uint32_t b_off = (uint32_t)(((sel >> 1) * 8 + ln) * ASTRB + (sel & 1) * 16);

    float acc[16][4];
    #pragma unroll
    for (int t = 0; t < 16; t++)
        #pragma unroll
        for (int j = 0; j < 4; j++) acc[t][j] = 0.f;

    auto issue = [&](int kc, int s) {
        const int k0 = kc * 32;
        const uint32_t st = sbase + s * STAGE;
        uint32_t sa = st + saoff;
        cp16(sa,            Xh + gaA + k0);
        cp16(sa + 16,       Xh + gaA + k0 + 8);
        cp16(sa + ARR,      Xl + gaA + k0);
        cp16(sa + ARR + 16, Xl + gaA + k0 + 8);
        sa += 2 * ARR;
        cp16(sa,            Wh + gaB + k0);
        cp16(sa + 16,       Wh + gaB + k0 + 8);
        cp16(sa + ARR,      Wl + gaB + k0);
        cp16(sa + ARR + 16, Wl + gaB + k0 + 8);
    };

    issue(0, 0); CP_COMMIT();
    issue(1, 1); CP_COMMIT();

    for (int kc = 0; kc < 8; kc++) {
        const int s = kc & 1;
        if (kc < 7) asm volatile("cp.async.wait_group 1;" ::: "memory");
        else        asm volatile("cp.async.wait_group 0;" ::: "memory");
        __syncthreads();
        const uint32_t st = sbase + s * STAGE;
        #pragma unroll
        for (int ks = 0; ks < 2; ks++) {
            const uint32_t koff = (uint32_t)(ks * 32);
            uint32_t ah[4], al[4];
            ldm_x4(ah, st + a_off + koff);
            ldm_x4(al, st + ARR + a_off + koff);
            #pragma unroll
            for (int tp = 0; tp < 8; tp++) {
                const int t = tp * 2;
                uint32_t bh4[4], bl4[4];
                const uint32_t ba = st + 2 * ARR + b_off + koff + (uint32_t)t * (8 * ASTRB);
                ldm_x4(bh4, ba);
                ldm_x4(bl4, ba + ARR);
                mma_bf16(acc[t],     ah, &bh4[0], acc[t]);
                mma_bf16(acc[t],     ah, &bl4[0], acc[t]);
                mma_bf16(acc[t],     al, &bh4[0], acc[t]);
                mma_bf16(acc[t + 1], ah, &bh4[2], acc[t + 1]);
                mma_bf16(acc[t + 1], ah, &bl4[2], acc[t + 1]);
                mma_bf16(acc[t + 1], al, &bh4[2], acc[t + 1]);
            }
        }
        __syncthreads();
        if (kc + 2 < 8) { issue(kc + 2, s); CP_COMMIT(); }
    }

    int row0 = bm + wrow + r;
    int row1 = row0 + 8;
    float sd0[2] = {0.f, 0.f}, sd1[2] = {0.f, 0.f};
    float dd0[2] = {0.f, 0.f}, dd1[2] = {0.f, 0.f};
    #pragma unroll
    for (int t = 0; t < 16; t++) {
        int c0 = t * 8 + q * 2;
        int hh = t >> 3;
        sd0[hh] += acc[t][0] * AS[c0] + acc[t][1] * AS[c0 + 1];
        dd0[hh] += acc[t][0] * AD[c0] + acc[t][1] * AD[c0 + 1];
        sd1[hh] += acc[t][2] * AS[c0] + acc[t][3] * AS[c0 + 1];
        dd1[hh] += acc[t][2] * AD[c0] + acc[t][3] * AD[c0 + 1];
        if (row0 < M)
            *(__half2*)(Ch + (size_t)row0 * F1 + bn + c0) =
                __floats2half2_rn(acc[t][0], acc[t][1]);
        if (row1 < M)
            *(__half2*)(Ch + (size_t)row1 * F1 + bn + c0) =
                __floats2half2_rn(acc[t][2], acc[t][3]);
    }
    #pragma unroll
    for (int o = 1; o < 4; o <<= 1) {
        #pragma unroll
        for (int hh = 0; hh < 2; hh++) {
            sd0[hh] += __shfl_xor_sync(0xFFFFFFFFu, sd0[hh], o);
            sd1[hh] += __shfl_xor_sync(0xFFFFFFFFu, sd1[hh], o);
            dd0[hh] += __shfl_xor_sync(0xFFFFFFFFu, dd0[hh], o);
            dd1[hh] += __shfl_xor_sync(0xFFFFFFFFu, dd1[hh], o);
        }
    }
    if (q == 0) {
        int hb = (blockIdx.x & 1) * 2;
        if (row0 < M) {
            es[row0 * HEADS + hb]     = sd0[0];
            es[row0 * HEADS + hb + 1] = sd0[1];
            ed[row0 * HEADS + hb]     = dd0[0];
            ed[row0 * HEADS + hb + 1] = dd0[1];
        }
        if (row1 < M) {
            es[row1 * HEADS + hb]     = sd1[0];
            es[row1 * HEADS + hb + 1] = sd1[1];
            ed[row1 * HEADS + hb]     = dd1[0];
            ed[row1 * HEADS + hb + 1] = dd1[1];
        }
    }
}

// ---------- layer-2 GEMM: HMMA, N=64 ----------
#define BARR2  (64 * ASTRB)
#define STAGE2 (2 * ARR + 2 * BARR2)
__global__ void __launch_bounds__(256, 2)
gemm2_mma_kernel(const __nv_bfloat16* __restrict__ Ahg, const __nv_bfloat16* __restrict__ Alg,
                 const __nv_bfloat16* __restrict__ Wh, const __nv_bfloat16* __restrict__ Wl,
                 float* __restrict__ C, int M,
                 const float* __restrict__ a_src, const float* __restrict__ a_dst,
                 float* __restrict__ es, float* __restrict__ ed) {
    extern __shared__ char smem[];
    __shared__ float AS[64], AD[64];

    const int tid = threadIdx.x;
    const int w = tid >> 5, lane = tid & 31;
    const int q = lane & 3, r = lane >> 2;
    const int bm = blockIdx.y * 128;
    const int wrow = w * 16;

    if (tid < 64) {
        AS[tid] = a_src[tid];
        AD[tid] = a_dst[tid];
    }
    const uint32_t sbase = smem_u32(smem);

    const int lrow = tid >> 1;
    const int lce = (tid & 1) * 16;
    const size_t gaA = (size_t)(bm + lrow) * F1 + lce;
    const uint32_t saoff = (uint32_t)(lrow * ASTRB + lce * 2);
    const int brow = (tid & 127) >> 1;
    const int bce = (tid & 1) * 16;
    const size_t gaB = (size_t)brow * F1 + bce;
    const uint32_t sboff = (uint32_t)(brow * ASTRB + bce * 2);

    const int ln  = lane & 7;
    const int sel = lane >> 3;
    const uint32_t a_off = (uint32_t)((wrow + ln + (sel & 1) * 8) * ASTRB + (sel >> 1) * 16);
    const uint32_t b_off = (uint32_t)(((sel >> 1) * 8 + ln) * ASTRB + (sel & 1) * 16);

    float acc[8][4];
    #pragma unroll
    for (int t = 0; t < 8; t++)
        #pragma unroll
        for (int j = 0; j < 4; j++) acc[t][j] = 0.f;

    auto issue = [&](int kc, int s) {
        const int k0 = kc * 32;
        const uint32_t st = sbase + s * STAGE2;
        uint32_t sa = st + saoff;
        cp16(sa,            Ahg + gaA + k0);
        cp16(sa + 16,       Ahg + gaA + k0 + 8);
        cp16(sa + ARR,      Alg + gaA + k0);
        cp16(sa + ARR + 16, Alg + gaA + k0 + 8);
        if (tid < 128) {
            uint32_t sb = st + 2 * ARR + sboff;
            cp16(sb,              Wh + gaB + k0);
            cp16(sb + 16,         Wh + gaB + k0 + 8);
            cp16(sb + BARR2,      Wl + gaB + k0);
            cp16(sb + BARR2 + 16, Wl + gaB + k0 + 8);
        }
    };

    issue(0, 0); CP_COMMIT();
    issue(1, 1); CP_COMMIT();

    for (int kc = 0; kc < 8; kc++) {
        const int s = kc & 1;
        if (kc < 7) asm volatile("cp.async.wait_group 1;" ::: "memory");
        else        asm volatile("cp.async.wait_group 0;" ::: "memory");
        __syncthreads();
        const uint32_t st = sbase + s * STAGE2;
        #pragma unroll
        for (int ks = 0; ks < 2; ks++) {
            const uint32_t koff = (uint32_t)(ks * 32);
            uint32_t ah[4], al[4];
            ldm_x4(ah, st + a_off + koff);
            ldm_x4(al, st + ARR + a_off + koff);
            #pragma unroll
            for (int tp = 0; tp < 4; tp++) {
                const int t = tp * 2;
                uint32_t bh4[4], bl4[4];
                const uint32_t ba = st + 2 * ARR + b_off + koff + (uint32_t)t * (8 * ASTRB);
                ldm_x4(bh4, ba);
                ldm_x4(bl4, ba + BARR2);
                mma_bf16(acc[t],     ah, &bh4[0], acc[t]);
                mma_bf16(acc[t],     ah, &bl4[0], acc[t]);
                mma_bf16(acc[t],     al, &bh4[0], acc[t]);
                mma_bf16(acc[t + 1], ah, &bh4[2], acc[t + 1]);
                mma_bf16(acc[t + 1], ah, &bl4[2], acc[t + 1]);
                mma_bf16(acc[t + 1], al, &bh4[2], acc[t + 1]);
            }
        }
        __syncthreads();
        if (kc + 2 < 8) { issue(kc + 2, s); CP_COMMIT(); }
    }

    int row0 = bm + wrow + r;
    int row1 = row0 + 8;
    float sd0 = 0.f, sd1 = 0.f, dd0 = 0.f, dd1 = 0.f;
    #pragma unroll
    for (int t = 0; t < 8; t++) {
        int c0 = t * 8 + q * 2;
        sd0 += acc[t][0] * AS[c0] + acc[t][1] * AS[c0 + 1];
        dd0 += acc[t][0] * AD[c0] + acc[t][1] * AD[c0 + 1];
        sd1 += acc[t][2] * AS[c0] + acc[t][3] * AS[c0 + 1];
        dd1 += acc[t][2] * AD[c0] + acc[t][3] * AD[c0 + 1];
        if (row0 < M)
            *(float2*)(C + (size_t)row0 * OUT_C + c0) = make_float2(acc[t][0], acc[t][1]);
        if (row1 < M)
            *(float2*)(C + (size_t)row1 * OUT_C + c0) = make_float2(acc[t][2], acc[t][3]);
    }
    #pragma unroll
    for (int o = 1; o < 4; o <<= 1) {
        sd0 += __shfl_xor_sync(0xFFFFFFFFu, sd0, o);
        sd1 += __shfl_xor_sync(0xFFFFFFFFu, sd1, o);
        dd0 += __shfl_xor_sync(0xFFFFFFFFu, dd0, o);
        dd1 += __shfl_xor_sync(0xFFFFFFFFu, dd1, o);
    }
    if (q == 0) {
        if (row0 < M) { es[row0] = sd0; ed[row0] = dd0; }
        if (row1 < M) { es[row1] = sd1; ed[row1] = dd1; }
    }
}

// ---------------- layer-1 aggregation: warp per node, smem-staged (s, p) ----------------
__global__ void agg1_kernel(const int* __restrict__ off, const int* __restrict__ csr,
                            const __half* __restrict__ hh16,
                            const float* __restrict__ es, const float* __restrict__ ed,
                            const float* __restrict__ b1,
                            __nv_bfloat16* __restrict__ oh, __nv_bfloat16* __restrict__ ol) {
    __shared__ float sp[8][128];   // per warp: 32 edges x 4 heads
    __shared__ int   ss[8][32];
    int n = (blockIdx.x * blockDim.x + threadIdx.x) >> 5;
    int lane = threadIdx.x & 31;
    int wid = (threadIdx.x >> 5);
    if (n >= N_NODES) return;
    const int myh = lane >> 3;
    int beg = off[n], end = off[n + 1];
    float4 edn = *(const float4*)(ed + n * 4);
    float acc[8];
    #pragma unroll
    for (int k = 0; k < 8; k++) acc[k] = 0.f;
    float zsum = 0.f;

    for (int base = beg; base < end; base += 32) {
        int m = min(32, end - base);
        if (base + lane < end) {
            int sl = csr[base + lane];
            float4 e4 = *(const float4*)(es + sl * 4);
            float l0 = e4.x + edn.x; l0 = l0 > 0.f ? l0 : 0.2f * l0;
            float l1 = e4.y + edn.y; l1 = l1 > 0.f ? l1 : 0.2f * l1;
            float l2 = e4.z + edn.z; l2 = l2 > 0.f ? l2 : 0.2f * l2;
            float l3 = e4.w + edn.w; l3 = l3 > 0.f ? l3 : 0.2f * l3;
            float4 p4;
            p4.x = expf(l0); p4.y = expf(l1); p4.z = expf(l2); p4.w = expf(l3);
            *(float4*)&sp[wid][lane * 4] = p4;
            ss[wid][lane] = sl;
        }
        __syncwarp();
        for (int j = 0; j < m; j++) {
            int s = ss[wid][j];
            float p = sp[wid][j * 4 + myh];
            zsum += p;
            uint4 hv = *(const uint4*)(hh16 + (size_t)s * F1 + lane * 8);
            float2 f0 = __half22float2(*(__half2*)&hv.x);
            float2 f1 = __half22float2(*(__half2*)&hv.y);
            float2 f2 = __half22float2(*(__half2*)&hv.z);
            float2 f3 = __half22float2(*(__half2*)&hv.w);
            acc[0] += p * f0.x; acc[1] += p * f0.y;
            acc[2] += p * f1.x; acc[3] += p * f1.y;
            acc[4] += p * f2.x; acc[5] += p * f2.y;
            acc[6] += p * f3.x; acc[7] += p * f3.y;
        }
        __syncwarp();
    }
    float inv = 1.f / zsum;
    int c = lane * 8;
    __nv_bfloat16 hs[8], ls[8];
    #pragma unroll
    for (int k = 0; k < 8; k++) {
        float o = acc[k] * inv + b1[c + k];
        o = o > 0.f ? o : expm1f(o);
        hs[k] = __float2bfloat16(o);
        ls[k] = __float2bfloat16(o - __bfloat162float(hs[k]));
    }
    *(uint4*)(oh + (size_t)n * F1 + c) = *(uint4*)hs;
    *(uint4*)(ol + (size_t)n * F1 + c) = *(uint4*)ls;
}

// ---------------- layer-2 aggregation: warp per node, smem-staged (s, p) ----------------
__global__ void agg2_kernel(const int* __restrict__ off, const int* __restrict__ csr,
                            const float* __restrict__ h2,
                            const float* __restrict__ es, const float* __restrict__ ed,
                            const float* __restrict__ b2, float* __restrict__ out) {
    __shared__ float sp[8][32];
    __shared__ int   ss[8][32];
    int n = (blockIdx.x * blockDim.x + threadIdx.x) >> 5;
    int lane = threadIdx.x & 31;
    int wid = (threadIdx.x >> 5);
    if (n >= N_NODES) return;
    int beg = off[n], end = off[n + 1];
    float edn = ed[n];
    float accx = 0.f, accy = 0.f, zsum = 0.f;
    for (int base = beg; base < end; base += 32) {
        int m = min(32, end - base);
        if (base + lane < end) {
            int sl = csr[base + lane];
            float l = es[sl] + edn;
            l = l > 0.f ? l : 0.2f * l;
            sp[wid][lane] = expf(l);
            ss[wid][lane] = sl;
        }
        __syncwarp();
        for (int j = 0; j < m; j++) {
            int s = ss[wid][j];
            float p = sp[wid][j];
            zsum += p;
            float2 v = *(const float2*)(h2 + (size_t)s * OUT_C + lane * 2);
            accx += p * v.x;
            accy += p * v.y;
        }
        __syncwarp();
    }
    float inv = 1.f / zsum;
    float2 r;
    r.x = accx * inv + b2[lane * 2];
    r.y = accy * inv + b2[lane * 2 + 1];
    *(float2*)(out + (size_t)n * OUT_C + lane * 2) = r;
}

extern "C" void kernel_launch(void* const* d_in, const int* in_sizes, int n_in,
                              void* d_out, int out_size) {
    const float* x    = (const float*)d_in[0];
    const int*   ei   = (const int*)d_in[1];
    const float* W1   = (const float*)d_in[2];
    const float* a1s  = (const float*)d_in[3];
    const float* a1d  = (const float*)d_in[4];
    const float* b1   = (const float*)d_in[5];
    const float* W2   = (const float*)d_in[6];
    const float* a2s  = (const float*)d_in[7];
    const float* a2d  = (const float*)d_in[8];
    const float* b2   = (const float*)d_in[9];
    float* out = (float*)d_out;

    float *h2, *e1s, *e1d, *e2s, *e2d;
    int *cnt, *off, *rank, *csr;
    __half *h1h;
    __nv_bfloat16 *o1h, *o1l, *xh, *xl, *wh, *wl, *w2h, *w2l;
    cudaGetSymbolAddress((void**)&h1h, g_h1h);
    cudaGetSymbolAddress((void**)&o1h, g_o1h);
    cudaGetSymbolAddress((void**)&o1l, g_o1l);
    cudaGetSymbolAddress((void**)&h2,  g_h2);
    cudaGetSymbolAddress((void**)&e1s, g_e1s);
    cudaGetSymbolAddress((void**)&e1d, g_e1d);
    cudaGetSymbolAddress((void**)&e2s, g_e2s);
    cudaGetSymbolAddress((void**)&e2d, g_e2d);
    cudaGetSymbolAddress((void**)&cnt, g_cnt);
    cudaGetSymbolAddress((void**)&off, g_off);
    cudaGetSymbolAddress((void**)&rank, g_rank);
    cudaGetSymbolAddress((void**)&csr, g_csr);
    cudaGetSymbolAddress((void**)&xh, g_xh);
    cudaGetSymbolAddress((void**)&xl, g_xl);
    cudaGetSymbolAddress((void**)&wh, g_wh);
    cudaGetSymbolAddress((void**)&wl, g_wl);
    cudaGetSymbolAddress((void**)&w2h, g_w2h);
    cudaGetSymbolAddress((void**)&w2l, g_w2l);

    cudaFuncSetAttribute(gemm1_fill_kernel,
                         cudaFuncAttributeMaxDynamicSharedMemorySize, 2 * STAGE);
    cudaFuncSetAttribute(gemm2_mma_kernel,
                         cudaFuncAttributeMaxDynamicSharedMemorySize, 2 * STAGE2);

    cudaMemsetAsync(cnt, 0, N_NODES * sizeof(int));

    prep_kernel<<<(unsigned)(CONVX_BLOCKS + CONVW_BLOCKS + COUNT_BLOCKS), 256>>>(
        x, xh, xl, W1, W2, wh, wl, w2h, w2l, ei, cnt, rank);

    scan_kernel<<<1, 1024>>>(cnt, off, csr);

    gemm1_fill_kernel<<<GEMM1_BLOCKS + FILL_BLOCKS, 256, 2 * STAGE>>>(
        xh, xl, wh, wl, h1h, N_NODES, a1s, a1d, e1s, e1d, ei, off, rank, csr);

    // launch 3: agg1 (profiled by ncu)
    agg1_kernel<<<(N_NODES * 32 + 255) / 256, 256>>>(off, csr, h1h,
                                                     e1s, e1d, b1, o1h, o1l);

    {
        dim3 grid(1, (N_NODES + 127) / 128);
        gemm2_mma_kernel<<<grid, 256, 2 * STAGE2>>>(o1h, o1l, w2h, w2l, h2,
                                                    N_NODES, a2s, a2d, e2s, e2d);
    }
    agg2_kernel<<<(N_NODES * 32 + 255) / 256, 256>>>(off, csr, h2,
                                                     e2s, e2d, b2, out);
}